// round 6
// baseline (speedup 1.0000x reference)
#include <cuda_runtime.h>
#include <cuda_bf16.h>
#include <mma.h>
#include <math.h>
#include <cstdint>

using namespace nvcuda;

#define BATCH  16
#define CCH    512
#define LSP    1024
#define NHEADS 8

typedef __nv_bfloat16 bf16;
typedef __nv_bfloat162 bf162;

// ---------------- scratch (static device globals; no allocs) ----------------
__device__ bf16 g_xn[BATCH * CCH * LSP];
__device__ bf16 g_cn[BATCH * CCH * LSP];
__device__ bf16 g_q [BATCH * CCH * LSP];
__device__ bf16 g_kv[BATCH * 2 * CCH * LSP];
__device__ bf16 g_o [BATCH * CCH * LSP];
__device__ bf16 g_wq [CCH * CCH];
__device__ bf16 g_wkv[2 * CCH * CCH];
__device__ bf16 g_wp [CCH * CCH];

__device__ __forceinline__ unsigned int smem_u32(const void* p) {
    return (unsigned int)__cvta_generic_to_shared(p);
}
#define CP_ASYNC16(dst, src) \
    asm volatile("cp.async.cg.shared.global [%0], [%1], 16;\n" :: "r"(dst), "l"(src))
#define CP_COMMIT() asm volatile("cp.async.commit_group;\n" ::)
#define CP_WAIT1()  asm volatile("cp.async.wait_group 1;\n" ::)
#define CP_WAIT0()  asm volatile("cp.async.wait_group 0;\n" ::)

// ---------------- fp32 -> bf16 weight conversion ----------------
__global__ __launch_bounds__(256) void cvt_kernel(const float* __restrict__ src,
                                                  bf16* __restrict__ dst, int n4)
{
    int i = blockIdx.x * 256 + threadIdx.x;
    if (i < n4) {
        float4 v = ((const float4*)src)[i];
        ((bf162*)dst)[2 * i]     = __floats2bfloat162_rn(v.x, v.y);
        ((bf162*)dst)[2 * i + 1] = __floats2bfloat162_rn(v.z, v.w);
    }
}

// ---------------- GroupNorm (fp32 in, bf16 out) ----------------
__global__ __launch_bounds__(256) void gn_kernel(const float* __restrict__ x,
                                                 const float* __restrict__ w,
                                                 const float* __restrict__ bb,
                                                 bf16* __restrict__ out)
{
    int bg = blockIdx.x;
    int g  = bg & 31;
    const float4* x4 = (const float4*)(x + (size_t)bg * 16384);
    bf162*        o2 = (bf162*)(out + (size_t)bg * 16384);
    int tid = threadIdx.x;

    float s = 0.f, ss = 0.f;
    for (int i = tid; i < 4096; i += 256) {
        float4 v = x4[i];
        s  += v.x + v.y + v.z + v.w;
        ss += v.x*v.x + v.y*v.y + v.z*v.z + v.w*v.w;
    }
    __shared__ float rs[8], rss[8];
    #pragma unroll
    for (int o = 16; o; o >>= 1) {
        s  += __shfl_xor_sync(~0u, s, o);
        ss += __shfl_xor_sync(~0u, ss, o);
    }
    if ((tid & 31) == 0) { rs[tid >> 5] = s; rss[tid >> 5] = ss; }
    __syncthreads();
    if (tid < 32) {
        s  = (tid < 8) ? rs[tid]  : 0.f;
        ss = (tid < 8) ? rss[tid] : 0.f;
        #pragma unroll
        for (int o = 4; o; o >>= 1) {
            s  += __shfl_xor_sync(~0u, s, o);
            ss += __shfl_xor_sync(~0u, ss, o);
        }
        if (tid == 0) { rs[0] = s; rss[0] = ss; }
    }
    __syncthreads();
    float mean = rs[0] * (1.f / 16384.f);
    float var  = rss[0] * (1.f / 16384.f) - mean * mean;
    float inv  = rsqrtf(var + 1e-5f);

    for (int i = tid; i < 4096; i += 256) {
        int c = g * 16 + (i >> 8);
        float sc = w[c] * inv;
        float sh = bb[c] - mean * sc;
        float4 v = x4[i];
        o2[2 * i]     = __floats2bfloat162_rn(v.x * sc + sh, v.y * sc + sh);
        o2[2 * i + 1] = __floats2bfloat162_rn(v.z * sc + sh, v.w * sc + sh);
    }
}

// ---------------- conv1x1 GEMM, bf16 HMMA + cp.async double buffer ----------
// out[b,o,l] = sum_c W[o,c] * in[b,c,l] + bias[o] (+ resid for fp32 out)
// Block tile 128(O) x 128(L), BK=32, 2-stage cp.async pipeline.
#define ASTR 40
#define BSTR 136

template<bool BF16OUT>
__global__ __launch_bounds__(256) void gemm_bf(const bf16* __restrict__ in,
                                               const bf16* __restrict__ W,
                                               const float* __restrict__ bias,
                                               const float* __restrict__ resid,
                                               void* __restrict__ outp,
                                               int C, int O)
{
    __shared__ bf16  As[2][128 * ASTR];
    __shared__ bf16  Bs[2][32 * BSTR];
    __shared__ float Es[8 * 16 * 20];

    int b  = blockIdx.z;
    int o0 = blockIdx.y * 128;
    int l0 = blockIdx.x * 128;
    int tid = threadIdx.x, wid = tid >> 5, lane = tid & 31;
    int wm = wid >> 2, wn = wid & 3;

    const bf16* inb = in + (size_t)b * C * LSP;

    // cp.async mapping: A row ar (0..127), 16 bf16 at ac; B row br (0..31), 16 bf16 at bc
    int ar = tid >> 1, ac = (tid & 1) * 16;
    int br = tid >> 3, bc = (tid & 7) * 16;

    const bf16* Asrc = W   + (size_t)(o0 + ar) * C   + ac;
    const bf16* Bsrc = inb + (size_t)br        * LSP + l0 + bc;

    unsigned int Adst[2], Bdst[2];
    #pragma unroll
    for (int s = 0; s < 2; s++) {
        Adst[s] = smem_u32(&As[s][ar * ASTR + ac]);
        Bdst[s] = smem_u32(&Bs[s][br * BSTR + bc]);
    }

    wmma::fragment<wmma::accumulator, 16, 16, 16, float> acc[4][2];
    #pragma unroll
    for (int i = 0; i < 4; i++)
        #pragma unroll
        for (int j = 0; j < 2; j++) wmma::fill_fragment(acc[i][j], 0.f);

    const int T = C / 32;

    // prologue: stage tile 0
    CP_ASYNC16(Adst[0],      Asrc);
    CP_ASYNC16(Adst[0] + 16, Asrc + 8);
    CP_ASYNC16(Bdst[0],      Bsrc);
    CP_ASYNC16(Bdst[0] + 16, Bsrc + 8);
    CP_COMMIT();

    for (int it = 0; it < T; it++) {
        int s = it & 1;
        if (it + 1 < T) {
            int ns = s ^ 1;
            const bf16* An = Asrc + (it + 1) * 32;
            const bf16* Bn = Bsrc + (size_t)(it + 1) * 32 * LSP;
            CP_ASYNC16(Adst[ns],      An);
            CP_ASYNC16(Adst[ns] + 16, An + 8);
            CP_ASYNC16(Bdst[ns],      Bn);
            CP_ASYNC16(Bdst[ns] + 16, Bn + 8);
            CP_COMMIT();
            CP_WAIT1();
        } else {
            CP_WAIT0();
        }
        __syncthreads();

        #pragma unroll
        for (int ks = 0; ks < 2; ks++) {
            wmma::fragment<wmma::matrix_a, 16, 16, 16, bf16, wmma::row_major> af[4];
            wmma::fragment<wmma::matrix_b, 16, 16, 16, bf16, wmma::row_major> bfr[2];
            #pragma unroll
            for (int mi = 0; mi < 4; mi++)
                wmma::load_matrix_sync(af[mi], &As[s][(wm * 64 + mi * 16) * ASTR + ks * 16], ASTR);
            #pragma unroll
            for (int ni = 0; ni < 2; ni++)
                wmma::load_matrix_sync(bfr[ni], &Bs[s][(ks * 16) * BSTR + wn * 32 + ni * 16], BSTR);
            #pragma unroll
            for (int mi = 0; mi < 4; mi++)
                #pragma unroll
                for (int ni = 0; ni < 2; ni++)
                    wmma::mma_sync(acc[mi][ni], af[mi], bfr[ni], acc[mi][ni]);
        }
        __syncthreads();   // all reads of buffer s done before it is re-staged
    }

    // epilogue: frag -> smem -> bias(+resid) -> global
    #pragma unroll
    for (int mi = 0; mi < 4; mi++) {
        #pragma unroll
        for (int ni = 0; ni < 2; ni++) {
            wmma::store_matrix_sync(&Es[wid * 320], acc[mi][ni], 20, wmma::mem_row_major);
            __syncwarp();
            int r  = lane >> 1;
            int c8 = (lane & 1) * 8;
            int o  = o0 + wm * 64 + mi * 16 + r;
            int lg = l0 + wn * 32 + ni * 16 + c8;
            float bi = bias[o];
            size_t base = ((size_t)b * O + o) * LSP + lg;
            float v[8];
            #pragma unroll
            for (int j = 0; j < 8; j++) v[j] = Es[wid * 320 + r * 20 + c8 + j] + bi;
            if (BF16OUT) {
                __align__(16) bf16 t[8];
                #pragma unroll
                for (int j = 0; j < 8; j++) t[j] = __float2bfloat16(v[j]);
                *(uint4*)((bf16*)outp + base) = *(uint4*)t;
            } else {
                float* outf = (float*)outp;
                if (resid) {
                    float4 r0 = *(const float4*)&resid[base];
                    float4 r1 = *(const float4*)&resid[base + 4];
                    v[0] += r0.x; v[1] += r0.y; v[2] += r0.z; v[3] += r0.w;
                    v[4] += r1.x; v[5] += r1.y; v[6] += r1.z; v[7] += r1.w;
                }
                float4 w0 = {v[0], v[1], v[2], v[3]};
                float4 w1 = {v[4], v[5], v[6], v[7]};
                *(float4*)&outf[base]     = w0;
                *(float4*)&outf[base + 4] = w1;
            }
            __syncwarp();
        }
    }
}

// ---------------- attention: raw mma.sync, P in registers (unchanged) ------
#define QI 136   // Qs / OT row stride (bf16)
#define KJ 72    // Ks / Vs row stride (bf16)

#define LDSM4(r0,r1,r2,r3,addr) \
    asm volatile("ldmatrix.sync.aligned.m8n8.x4.shared.b16 {%0,%1,%2,%3},[%4];" \
        : "=r"(r0),"=r"(r1),"=r"(r2),"=r"(r3) : "r"(addr))
#define LDSM4T(r0,r1,r2,r3,addr) \
    asm volatile("ldmatrix.sync.aligned.m8n8.x4.trans.shared.b16 {%0,%1,%2,%3},[%4];" \
        : "=r"(r0),"=r"(r1),"=r"(r2),"=r"(r3) : "r"(addr))
#define MMA16816(c,a,b0,b1) \
    asm volatile("mma.sync.aligned.m16n8k16.row.col.f32.bf16.bf16.f32 " \
        "{%0,%1,%2,%3},{%4,%5,%6,%7},{%8,%9},{%0,%1,%2,%3};" \
        : "+f"(c[0]),"+f"(c[1]),"+f"(c[2]),"+f"(c[3]) \
        : "r"(a[0]),"r"(a[1]),"r"(a[2]),"r"(a[3]),"r"(b0),"r"(b1))

__device__ __forceinline__ unsigned int packbf2(float a, float b) {
    bf162 t = __floats2bfloat162_rn(a, b);
    return *(unsigned int*)&t;
}

__global__ __launch_bounds__(256) void attn_mma(const bf16* __restrict__ qb,
                                                const bf16* __restrict__ kvb,
                                                bf16* __restrict__ ob)
{
    __shared__ bf16 Qs[64 * QI];   // Qs[d][i] (128 i); reused as OT[d][i] at end
    __shared__ bf16 Ks[64 * KJ];   // Ks[d][j]
    __shared__ bf16 Vs[64 * KJ];   // Vs[d][j]

    int i0 = blockIdx.x * 128;
    int h  = blockIdx.y;
    int b  = blockIdx.z;
    int tid = threadIdx.x, wid = tid >> 5, lane = tid & 31;
    int gid = lane >> 2, qtid = lane & 3;
    int ibase = wid * 16;
    int lg = lane >> 3, lr = lane & 7;

    const bf16* qp = qb  + ((size_t)b * CCH     + h * 64) * LSP;
    const bf16* kp = kvb + ((size_t)b * 2 * CCH + h * 64) * LSP;
    const bf16* vp = kvb + ((size_t)b * 2 * CCH + CCH + h * 64) * LSP;
    bf16*       op = ob  + ((size_t)b * CCH     + h * 64) * LSP;

    {
        int d = tid >> 2, c = (tid & 3) * 32;
        const uint4* s = (const uint4*)&qp[(size_t)d * LSP + i0 + c];
        uint4* t = (uint4*)&Qs[d * QI + c];
        t[0] = s[0]; t[1] = s[1]; t[2] = s[2]; t[3] = s[3];
    }
    __syncthreads();

    unsigned int qa[4][4];
    #pragma unroll
    for (int ks = 0; ks < 4; ks++) {
        int drow = ks * 16 + (lg >> 1) * 8 + lr;
        int icol = ibase + (lg & 1) * 8;
        unsigned int a = smem_u32(&Qs[drow * QI + icol]);
        LDSM4T(qa[ks][0], qa[ks][1], qa[ks][2], qa[ks][3], a);
    }

    float oacc[8][4] = {};
    float rl = 0.f, rh = 0.f;

    int dk = tid >> 2, ck = (tid & 3) * 16;
    uint4 kr0, kr1, vr0, vr1;
    {
        const uint4* ks_ = (const uint4*)&kp[(size_t)dk * LSP + ck];
        const uint4* vs_ = (const uint4*)&vp[(size_t)dk * LSP + ck];
        kr0 = ks_[0]; kr1 = ks_[1]; vr0 = vs_[0]; vr1 = vs_[1];
    }

    for (int kt = 0; kt < 16; kt++) {
        __syncthreads();
        *(uint4*)&Ks[dk * KJ + ck]     = kr0;
        *(uint4*)&Ks[dk * KJ + ck + 8] = kr1;
        *(uint4*)&Vs[dk * KJ + ck]     = vr0;
        *(uint4*)&Vs[dk * KJ + ck + 8] = vr1;
        __syncthreads();
        if (kt < 15) {
            int j0 = (kt + 1) * 64;
            const uint4* ks_ = (const uint4*)&kp[(size_t)dk * LSP + j0 + ck];
            const uint4* vs_ = (const uint4*)&vp[(size_t)dk * LSP + j0 + ck];
            kr0 = ks_[0]; kr1 = ks_[1]; vr0 = vs_[0]; vr1 = vs_[1];
        }

        float sacc[8][4] = {};
        #pragma unroll
        for (int ks = 0; ks < 4; ks++) {
            #pragma unroll
            for (int jp = 0; jp < 4; jp++) {
                int drow = ks * 16 + (lg & 1) * 8 + lr;
                int jcol = jp * 16 + (lg >> 1) * 8;
                unsigned int a = smem_u32(&Ks[drow * KJ + jcol]);
                unsigned int b0, b1, b2, b3;
                LDSM4T(b0, b1, b2, b3, a);
                MMA16816(sacc[jp * 2],     qa[ks], b0, b1);
                MMA16816(sacc[jp * 2 + 1], qa[ks], b2, b3);
            }
        }

        unsigned int pa[4][4];
        #pragma unroll
        for (int t = 0; t < 8; t++) {
            float e0 = __expf(sacc[t][0] * 0.125f);
            float e1 = __expf(sacc[t][1] * 0.125f);
            float e2 = __expf(sacc[t][2] * 0.125f);
            float e3 = __expf(sacc[t][3] * 0.125f);
            rl += e0 + e1;
            rh += e2 + e3;
            pa[t >> 1][(t & 1) * 2]     = packbf2(e0, e1);
            pa[t >> 1][(t & 1) * 2 + 1] = packbf2(e2, e3);
        }

        #pragma unroll
        for (int ks = 0; ks < 4; ks++) {
            #pragma unroll
            for (int dp = 0; dp < 4; dp++) {
                int drow = dp * 16 + (lg >> 1) * 8 + lr;
                int jcol = ks * 16 + (lg & 1) * 8;
                unsigned int a = smem_u32(&Vs[drow * KJ + jcol]);
                unsigned int b0, b1, b2, b3;
                LDSM4(b0, b1, b2, b3, a);
                MMA16816(oacc[dp * 2],     pa[ks], b0, b1);
                MMA16816(oacc[dp * 2 + 1], pa[ks], b2, b3);
            }
        }
    }

    rl += __shfl_xor_sync(~0u, rl, 1); rl += __shfl_xor_sync(~0u, rl, 2);
    rh += __shfl_xor_sync(~0u, rh, 1); rh += __shfl_xor_sync(~0u, rh, 2);
    float il = 1.f / rl, ih = 1.f / rh;

    #pragma unroll
    for (int t = 0; t < 8; t++) {
        int dcol = t * 8 + qtid * 2;
        Qs[dcol * QI + ibase + gid]           = __float2bfloat16(oacc[t][0] * il);
        Qs[(dcol + 1) * QI + ibase + gid]     = __float2bfloat16(oacc[t][1] * il);
        Qs[dcol * QI + ibase + gid + 8]       = __float2bfloat16(oacc[t][2] * ih);
        Qs[(dcol + 1) * QI + ibase + gid + 8] = __float2bfloat16(oacc[t][3] * ih);
    }
    __syncthreads();

    {
        int d = tid >> 2, c = (tid & 3) * 32;
        const uint4* s = (const uint4*)&Qs[d * QI + c];
        uint4* t = (uint4*)&op[(size_t)d * LSP + i0 + c];
        t[0] = s[0]; t[1] = s[1]; t[2] = s[2]; t[3] = s[3];
    }
}

// ---------------- launch ----------------
extern "C" void kernel_launch(void* const* d_in, const int* in_sizes, int n_in,
                              void* d_out, int out_size)
{
    const float* x   = (const float*)d_in[0];
    const float* ctx = (const float*)d_in[1];
    const float* nqw = (const float*)d_in[2];
    const float* nqb = (const float*)d_in[3];
    const float* nkw = (const float*)d_in[4];
    const float* nkb = (const float*)d_in[5];
    const float* cqw = (const float*)d_in[6];
    const float* cqb = (const float*)d_in[7];
    const float* ckw = (const float*)d_in[8];
    const float* ckb = (const float*)d_in[9];
    const float* pw  = (const float*)d_in[10];
    const float* pb  = (const float*)d_in[11];
    float* out = (float*)d_out;

    bf16 *xn, *cn, *q, *kv, *o, *wq, *wkv, *wp;
    cudaGetSymbolAddress((void**)&xn,  g_xn);
    cudaGetSymbolAddress((void**)&cn,  g_cn);
    cudaGetSymbolAddress((void**)&q,   g_q);
    cudaGetSymbolAddress((void**)&kv,  g_kv);
    cudaGetSymbolAddress((void**)&o,   g_o);
    cudaGetSymbolAddress((void**)&wq,  g_wq);
    cudaGetSymbolAddress((void**)&wkv, g_wkv);
    cudaGetSymbolAddress((void**)&wp,  g_wp);

    cvt_kernel<<<CCH * CCH / 1024, 256>>>(cqw, wq,  CCH * CCH / 4);
    cvt_kernel<<<2 * CCH * CCH / 1024, 256>>>(ckw, wkv, 2 * CCH * CCH / 4);
    cvt_kernel<<<CCH * CCH / 1024, 256>>>(pw,  wp,  CCH * CCH / 4);

    gn_kernel<<<BATCH * 32, 256>>>(x,   nqw, nqb, xn);
    gn_kernel<<<BATCH * 32, 256>>>(ctx, nkw, nkb, cn);

    gemm_bf<true><<<dim3(8, 4, BATCH), 256>>>(xn, wq,  cqb, nullptr, q,  CCH, CCH);
    gemm_bf<true><<<dim3(8, 8, BATCH), 256>>>(cn, wkv, ckb, nullptr, kv, CCH, 2 * CCH);

    attn_mma<<<dim3(8, NHEADS, BATCH), 256>>>(q, kv, o);

    gemm_bf<false><<<dim3(8, 4, BATCH), 256>>>(o, wp, pb, x, out, CCH, CCH);
}

// round 8
// speedup vs baseline: 1.1018x; 1.1018x over previous
#include <cuda_runtime.h>
#include <cuda_bf16.h>
#include <math.h>
#include <cstdint>

#define BATCH  16
#define CCH    512
#define LSP    1024
#define NHEADS 8

typedef __nv_bfloat16 bf16;
typedef __nv_bfloat162 bf162;

// ---------------- scratch (static device globals; no allocs) ----------------
__device__ bf16 g_xn[BATCH * CCH * LSP];
__device__ bf16 g_cn[BATCH * CCH * LSP];
__device__ bf16 g_q [BATCH * CCH * LSP];
__device__ bf16 g_kv[BATCH * 2 * CCH * LSP];
__device__ bf16 g_o [BATCH * CCH * LSP];
__device__ bf16 g_wq [CCH * CCH];
__device__ bf16 g_wkv[2 * CCH * CCH];
__device__ bf16 g_wp [CCH * CCH];

// ---------------- PTX helpers ----------------
__device__ __forceinline__ unsigned int smem_u32(const void* p) {
    return (unsigned int)__cvta_generic_to_shared(p);
}
#define CP_ASYNC16(dst, src) \
    asm volatile("cp.async.cg.shared.global [%0], [%1], 16;\n" :: "r"(dst), "l"(src))
#define CP_COMMIT() asm volatile("cp.async.commit_group;\n" ::)
#define CP_WAIT1()  asm volatile("cp.async.wait_group 1;\n" ::)
#define CP_WAIT0()  asm volatile("cp.async.wait_group 0;\n" ::)
#define LDSM4(r0,r1,r2,r3,addr) \
    asm volatile("ldmatrix.sync.aligned.m8n8.x4.shared.b16 {%0,%1,%2,%3},[%4];" \
        : "=r"(r0),"=r"(r1),"=r"(r2),"=r"(r3) : "r"(addr))
#define LDSM4T(r0,r1,r2,r3,addr) \
    asm volatile("ldmatrix.sync.aligned.m8n8.x4.trans.shared.b16 {%0,%1,%2,%3},[%4];" \
        : "=r"(r0),"=r"(r1),"=r"(r2),"=r"(r3) : "r"(addr))
#define MMA16816(c,a,b0,b1) \
    asm volatile("mma.sync.aligned.m16n8k16.row.col.f32.bf16.bf16.f32 " \
        "{%0,%1,%2,%3},{%4,%5,%6,%7},{%8,%9},{%0,%1,%2,%3};" \
        : "+f"(c[0]),"+f"(c[1]),"+f"(c[2]),"+f"(c[3]) \
        : "r"(a[0]),"r"(a[1]),"r"(a[2]),"r"(a[3]),"r"(b0),"r"(b1))

__device__ __forceinline__ unsigned int packbf2(float a, float b) {
    bf162 t = __floats2bfloat162_rn(a, b);
    return *(unsigned int*)&t;
}

// ---------------- fp32 -> bf16 weight conversion ----------------
__global__ __launch_bounds__(256) void cvt_kernel(const float* __restrict__ src,
                                                  bf16* __restrict__ dst, int n4)
{
    int i = blockIdx.x * 256 + threadIdx.x;
    if (i < n4) {
        float4 v = ((const float4*)src)[i];
        ((bf162*)dst)[2 * i]     = __floats2bfloat162_rn(v.x, v.y);
        ((bf162*)dst)[2 * i + 1] = __floats2bfloat162_rn(v.z, v.w);
    }
}

// ---------------- GroupNorm (fp32 in, bf16 out) ----------------
__global__ __launch_bounds__(256) void gn_kernel(const float* __restrict__ x,
                                                 const float* __restrict__ w,
                                                 const float* __restrict__ bb,
                                                 bf16* __restrict__ out)
{
    int bg = blockIdx.x;
    int g  = bg & 31;
    const float4* x4 = (const float4*)(x + (size_t)bg * 16384);
    bf162*        o2 = (bf162*)(out + (size_t)bg * 16384);
    int tid = threadIdx.x;

    float s = 0.f, ss = 0.f;
    for (int i = tid; i < 4096; i += 256) {
        float4 v = x4[i];
        s  += v.x + v.y + v.z + v.w;
        ss += v.x*v.x + v.y*v.y + v.z*v.z + v.w*v.w;
    }
    __shared__ float rs[8], rss[8];
    #pragma unroll
    for (int o = 16; o; o >>= 1) {
        s  += __shfl_xor_sync(~0u, s, o);
        ss += __shfl_xor_sync(~0u, ss, o);
    }
    if ((tid & 31) == 0) { rs[tid >> 5] = s; rss[tid >> 5] = ss; }
    __syncthreads();
    if (tid < 32) {
        s  = (tid < 8) ? rs[tid]  : 0.f;
        ss = (tid < 8) ? rss[tid] : 0.f;
        #pragma unroll
        for (int o = 4; o; o >>= 1) {
            s  += __shfl_xor_sync(~0u, s, o);
            ss += __shfl_xor_sync(~0u, ss, o);
        }
        if (tid == 0) { rs[0] = s; rss[0] = ss; }
    }
    __syncthreads();
    float mean = rs[0] * (1.f / 16384.f);
    float var  = rss[0] * (1.f / 16384.f) - mean * mean;
    float inv  = rsqrtf(var + 1e-5f);

    for (int i = tid; i < 4096; i += 256) {
        int c = g * 16 + (i >> 8);
        float sc = w[c] * inv;
        float sh = bb[c] - mean * sc;
        float4 v = x4[i];
        o2[2 * i]     = __floats2bfloat162_rn(v.x * sc + sh, v.y * sc + sh);
        o2[2 * i + 1] = __floats2bfloat162_rn(v.z * sc + sh, v.w * sc + sh);
    }
}

// ---------------- conv1x1 GEMM: raw mma.sync, BK=64, 3-stage cp.async ------
// out[b,o,l] = sum_c W[o,c] X[c,l] + bias[o] (+resid for fp32 out)
// Block 128(O) x 128(L); 8 warps = 4(m) x 2(n); warp tile 32 x 64.
// One __syncthreads per k-chunk (3-stage pipeline).
#define AS 72     // A row stride (bf16): [m][k] rows of 64 + 8 pad
#define BS 136    // B row stride (bf16): [k][n] rows of 128 + 8 pad
#define A_BYTES (128 * AS * 2)   // 18432
#define B_BYTES (64 * BS * 2)    // 17408
#define DS 132    // epilogue f32 row stride

template<bool BF16OUT>
__global__ __launch_bounds__(256) void gemm_mma(const bf16* __restrict__ in,
                                                const bf16* __restrict__ W,
                                                const float* __restrict__ bias,
                                                const float* __restrict__ resid,
                                                void* __restrict__ outp, int O)
{
    extern __shared__ char smraw[];
    bf16* Abuf[3]; bf16* Bbuf[3];
    #pragma unroll
    for (int s = 0; s < 3; s++) {
        Abuf[s] = (bf16*)(smraw + s * A_BYTES);
        Bbuf[s] = (bf16*)(smraw + 3 * A_BYTES + s * B_BYTES);
    }
    float* Ds = (float*)smraw;   // epilogue staging (aliases stage buffers)

    int b  = blockIdx.z;
    int o0 = blockIdx.y * 128;
    int l0 = blockIdx.x * 128;
    int tid = threadIdx.x, wid = tid >> 5, lane = tid & 31;
    int wm = wid >> 1, wn = wid & 1;
    int gid = lane >> 2, qtid = lane & 3;
    int lg = lane >> 3, lr = lane & 7;

    const bf16* Xb = in + (size_t)b * CCH * LSP;

    // stage chunk kc (A: 128x64, B: 64x128) into buffer set `s`
    auto stage = [&](int s, int kc) {
        const bf16* Aw = W  + (size_t)o0 * CCH + kc * 64;
        const bf16* Bx = Xb + (size_t)(kc * 64) * LSP + l0;
        #pragma unroll
        for (int t = 0; t < 4; t++) {        // A: 1024 16B-chunks / 256 thr
            int idx = tid + t * 256;
            int ar = idx >> 3, ac = (idx & 7) * 8;
            CP_ASYNC16(smem_u32(&Abuf[s][ar * AS + ac]), Aw + (size_t)ar * CCH + ac);
        }
        #pragma unroll
        for (int t = 0; t < 4; t++) {        // B: 1024 16B-chunks / 256 thr
            int idx = tid + t * 256;
            int br = idx >> 4, bc = (idx & 15) * 8;
            CP_ASYNC16(smem_u32(&Bbuf[s][br * BS + bc]), Bx + (size_t)br * LSP + bc);
        }
        CP_COMMIT();
    };

    float acc[2][8][4] = {};   // [mi][n8 tile][frag]

    const int T = CCH / 64;    // 8 chunks
    stage(0, 0);
    stage(1, 1);

    for (int i = 0; i < T; i++) {
        int s = i % 3;
        if (i == T - 1) { CP_WAIT0(); } else { CP_WAIT1(); }
        __syncthreads();   // chunk i staged; all warps done with buffer (i-1)%3

        #pragma unroll
        for (int ks = 0; ks < 4; ks++) {
            // A frags [m][k] row-major: quads g0(mL,kL) g1(mH,kL) g2(mL,kH) g3(mH,kH)
            unsigned int af[2][4];
            #pragma unroll
            for (int mi = 0; mi < 2; mi++) {
                int mrow = wm * 32 + mi * 16 + (lg & 1) * 8 + lr;
                int kcol = ks * 16 + (lg >> 1) * 8;
                LDSM4(af[mi][0], af[mi][1], af[mi][2], af[mi][3],
                      smem_u32(&Abuf[s][mrow * AS + kcol]));
            }
            // B frags [k][n] via ldsm.trans: g0(nL,kL) g1(nL,kH) g2(nH,kL) g3(nH,kH)
            #pragma unroll
            for (int np = 0; np < 4; np++) {
                int krow = ks * 16 + (lg & 1) * 8 + lr;
                int ncol = wn * 64 + np * 16 + (lg >> 1) * 8;
                unsigned int b0, b1, b2, b3;
                LDSM4T(b0, b1, b2, b3, smem_u32(&Bbuf[s][krow * BS + ncol]));
                #pragma unroll
                for (int mi = 0; mi < 2; mi++) {
                    MMA16816(acc[mi][np * 2],     af[mi], b0, b1);
                    MMA16816(acc[mi][np * 2 + 1], af[mi], b2, b3);
                }
            }
        }
        if (i + 2 < T) stage((i + 2) % 3, i + 2);
    }

    // epilogue: acc -> smem (f32 [128][DS]) -> coalesced global with bias/resid
    __syncthreads();   // all warps done reading stage buffers
    #pragma unroll
    for (int mi = 0; mi < 2; mi++) {
        int r0 = wm * 32 + mi * 16 + gid;
        #pragma unroll
        for (int t = 0; t < 8; t++) {
            int c = wn * 64 + t * 8 + qtid * 2;
            *(float2*)&Ds[r0 * DS + c]       = make_float2(acc[mi][t][0], acc[mi][t][1]);
            *(float2*)&Ds[(r0 + 8) * DS + c] = make_float2(acc[mi][t][2], acc[mi][t][3]);
        }
    }
    __syncthreads();

    {
        int r = tid >> 1, half = tid & 1;
        int o = o0 + r;
        float bi = bias[o];
        const float* src = &Ds[r * DS + half * 64];
        size_t base = ((size_t)b * O + o) * LSP + l0 + half * 64;
        if (BF16OUT) {
            __align__(16) bf16 tb[64];
            #pragma unroll
            for (int j = 0; j < 64; j++) tb[j] = __float2bfloat16(src[j] + bi);
            uint4* dst = (uint4*)((bf16*)outp + base);
            #pragma unroll
            for (int j = 0; j < 8; j++) dst[j] = ((uint4*)tb)[j];
        } else {
            float* dst = (float*)outp + base;
            const float4* rs_ = (const float4*)(resid + base);
            #pragma unroll
            for (int j = 0; j < 16; j++) {
                float4 rv = rs_[j];
                float4 w;
                w.x = src[j * 4 + 0] + bi + rv.x;
                w.y = src[j * 4 + 1] + bi + rv.y;
                w.z = src[j * 4 + 2] + bi + rv.z;
                w.w = src[j * 4 + 3] + bi + rv.w;
                ((float4*)dst)[j] = w;
            }
        }
    }
}

// ---------------- attention: raw mma.sync, P in registers (R5, unchanged) --
#define QI 136
#define KJ 72

__global__ __launch_bounds__(256) void attn_mma(const bf16* __restrict__ qb,
                                                const bf16* __restrict__ kvb,
                                                bf16* __restrict__ ob)
{
    __shared__ bf16 Qs[64 * QI];
    __shared__ bf16 Ks[64 * KJ];
    __shared__ bf16 Vs[64 * KJ];

    int i0 = blockIdx.x * 128;
    int h  = blockIdx.y;
    int b  = blockIdx.z;
    int tid = threadIdx.x, wid = tid >> 5, lane = tid & 31;
    int gid = lane >> 2, qtid = lane & 3;
    int ibase = wid * 16;
    int lg = lane >> 3, lr = lane & 7;

    const bf16* qp = qb  + ((size_t)b * CCH     + h * 64) * LSP;
    const bf16* kp = kvb + ((size_t)b * 2 * CCH + h * 64) * LSP;
    const bf16* vp = kvb + ((size_t)b * 2 * CCH + CCH + h * 64) * LSP;
    bf16*       op = ob  + ((size_t)b * CCH     + h * 64) * LSP;

    {
        int d = tid >> 2, c = (tid & 3) * 32;
        const uint4* s = (const uint4*)&qp[(size_t)d * LSP + i0 + c];
        uint4* t = (uint4*)&Qs[d * QI + c];
        t[0] = s[0]; t[1] = s[1]; t[2] = s[2]; t[3] = s[3];
    }
    __syncthreads();

    unsigned int qa[4][4];
    #pragma unroll
    for (int ks = 0; ks < 4; ks++) {
        int drow = ks * 16 + (lg >> 1) * 8 + lr;
        int icol = ibase + (lg & 1) * 8;
        unsigned int a = smem_u32(&Qs[drow * QI + icol]);
        LDSM4T(qa[ks][0], qa[ks][1], qa[ks][2], qa[ks][3], a);
    }

    float oacc[8][4] = {};
    float rl = 0.f, rh = 0.f;

    int dk = tid >> 2, ck = (tid & 3) * 16;
    uint4 kr0, kr1, vr0, vr1;
    {
        const uint4* ks_ = (const uint4*)&kp[(size_t)dk * LSP + ck];
        const uint4* vs_ = (const uint4*)&vp[(size_t)dk * LSP + ck];
        kr0 = ks_[0]; kr1 = ks_[1]; vr0 = vs_[0]; vr1 = vs_[1];
    }

    for (int kt = 0; kt < 16; kt++) {
        __syncthreads();
        *(uint4*)&Ks[dk * KJ + ck]     = kr0;
        *(uint4*)&Ks[dk * KJ + ck + 8] = kr1;
        *(uint4*)&Vs[dk * KJ + ck]     = vr0;
        *(uint4*)&Vs[dk * KJ + ck + 8] = vr1;
        __syncthreads();
        if (kt < 15) {
            int j0 = (kt + 1) * 64;
            const uint4* ks_ = (const uint4*)&kp[(size_t)dk * LSP + j0 + ck];
            const uint4* vs_ = (const uint4*)&vp[(size_t)dk * LSP + j0 + ck];
            kr0 = ks_[0]; kr1 = ks_[1]; vr0 = vs_[0]; vr1 = vs_[1];
        }

        float sacc[8][4] = {};
        #pragma unroll
        for (int ks = 0; ks < 4; ks++) {
            #pragma unroll
            for (int jp = 0; jp < 4; jp++) {
                int drow = ks * 16 + (lg & 1) * 8 + lr;
                int jcol = jp * 16 + (lg >> 1) * 8;
                unsigned int a = smem_u32(&Ks[drow * KJ + jcol]);
                unsigned int b0, b1, b2, b3;
                LDSM4T(b0, b1, b2, b3, a);
                MMA16816(sacc[jp * 2],     qa[ks], b0, b1);
                MMA16816(sacc[jp * 2 + 1], qa[ks], b2, b3);
            }
        }

        unsigned int pa[4][4];
        #pragma unroll
        for (int t = 0; t < 8; t++) {
            float e0 = __expf(sacc[t][0] * 0.125f);
            float e1 = __expf(sacc[t][1] * 0.125f);
            float e2 = __expf(sacc[t][2] * 0.125f);
            float e3 = __expf(sacc[t][3] * 0.125f);
            rl += e0 + e1;
            rh += e2 + e3;
            pa[t >> 1][(t & 1) * 2]     = packbf2(e0, e1);
            pa[t >> 1][(t & 1) * 2 + 1] = packbf2(e2, e3);
        }

        #pragma unroll
        for (int ks = 0; ks < 4; ks++) {
            #pragma unroll
            for (int dp = 0; dp < 4; dp++) {
                int drow = dp * 16 + (lg >> 1) * 8 + lr;
                int jcol = ks * 16 + (lg & 1) * 8;
                unsigned int a = smem_u32(&Vs[drow * KJ + jcol]);
                unsigned int b0, b1, b2, b3;
                LDSM4(b0, b1, b2, b3, a);
                MMA16816(oacc[dp * 2],     pa[ks], b0, b1);
                MMA16816(oacc[dp * 2 + 1], pa[ks], b2, b3);
            }
        }
    }

    rl += __shfl_xor_sync(~0u, rl, 1); rl += __shfl_xor_sync(~0u, rl, 2);
    rh += __shfl_xor_sync(~0u, rh, 1); rh += __shfl_xor_sync(~0u, rh, 2);
    float il = 1.f / rl, ih = 1.f / rh;

    #pragma unroll
    for (int t = 0; t < 8; t++) {
        int dcol = t * 8 + qtid * 2;
        Qs[dcol * QI + ibase + gid]           = __float2bfloat16(oacc[t][0] * il);
        Qs[(dcol + 1) * QI + ibase + gid]     = __float2bfloat16(oacc[t][1] * il);
        Qs[dcol * QI + ibase + gid + 8]       = __float2bfloat16(oacc[t][2] * ih);
        Qs[(dcol + 1) * QI + ibase + gid + 8] = __float2bfloat16(oacc[t][3] * ih);
    }
    __syncthreads();

    {
        int d = tid >> 2, c = (tid & 3) * 32;
        const uint4* s = (const uint4*)&Qs[d * QI + c];
        uint4* t = (uint4*)&op[(size_t)d * LSP + i0 + c];
        t[0] = s[0]; t[1] = s[1]; t[2] = s[2]; t[3] = s[3];
    }
}

// ---------------- launch ----------------
extern "C" void kernel_launch(void* const* d_in, const int* in_sizes, int n_in,
                              void* d_out, int out_size)
{
    const float* x   = (const float*)d_in[0];
    const float* ctx = (const float*)d_in[1];
    const float* nqw = (const float*)d_in[2];
    const float* nqb = (const float*)d_in[3];
    const float* nkw = (const float*)d_in[4];
    const float* nkb = (const float*)d_in[5];
    const float* cqw = (const float*)d_in[6];
    const float* cqb = (const float*)d_in[7];
    const float* ckw = (const float*)d_in[8];
    const float* ckb = (const float*)d_in[9];
    const float* pw  = (const float*)d_in[10];
    const float* pb  = (const float*)d_in[11];
    float* out = (float*)d_out;

    bf16 *xn, *cn, *q, *kv, *o, *wq, *wkv, *wp;
    cudaGetSymbolAddress((void**)&xn,  g_xn);
    cudaGetSymbolAddress((void**)&cn,  g_cn);
    cudaGetSymbolAddress((void**)&q,   g_q);
    cudaGetSymbolAddress((void**)&kv,  g_kv);
    cudaGetSymbolAddress((void**)&o,   g_o);
    cudaGetSymbolAddress((void**)&wq,  g_wq);
    cudaGetSymbolAddress((void**)&wkv, g_wkv);
    cudaGetSymbolAddress((void**)&wp,  g_wp);

    const int gsmem = 3 * (A_BYTES + B_BYTES);   // 107520 B
    cudaFuncSetAttribute(gemm_mma<true>,  cudaFuncAttributeMaxDynamicSharedMemorySize, gsmem);
    cudaFuncSetAttribute(gemm_mma<false>, cudaFuncAttributeMaxDynamicSharedMemorySize, gsmem);

    cvt_kernel<<<CCH * CCH / 1024, 256>>>(cqw, wq,  CCH * CCH / 4);
    cvt_kernel<<<2 * CCH * CCH / 1024, 256>>>(ckw, wkv, 2 * CCH * CCH / 4);
    cvt_kernel<<<CCH * CCH / 1024, 256>>>(pw,  wp,  CCH * CCH / 4);

    gn_kernel<<<BATCH * 32, 256>>>(x,   nqw, nqb, xn);
    gn_kernel<<<BATCH * 32, 256>>>(ctx, nkw, nkb, cn);

    gemm_mma<true><<<dim3(8, 4, BATCH), 256, gsmem>>>(xn, wq,  cqb, nullptr, q,  CCH);
    gemm_mma<true><<<dim3(8, 8, BATCH), 256, gsmem>>>(cn, wkv, ckb, nullptr, kv, 2 * CCH);

    attn_mma<<<dim3(8, NHEADS, BATCH), 256>>>(q, kv, o);

    gemm_mma<false><<<dim3(8, 4, BATCH), 256, gsmem>>>(o, wp, pb, x, out, CCH);
}

// round 9
// speedup vs baseline: 1.3286x; 1.2059x over previous
#include <cuda_runtime.h>
#include <cuda_bf16.h>
#include <math.h>
#include <cstdint>

#define BATCH  16
#define CCH    512
#define LSP    1024
#define NHEADS 8

typedef __nv_bfloat16 bf16;
typedef __nv_bfloat162 bf162;

// ---------------- scratch (static device globals; no allocs) ----------------
__device__ bf16 g_xn[BATCH * CCH * LSP];
__device__ bf16 g_cn[BATCH * CCH * LSP];
__device__ bf16 g_q [BATCH * CCH * LSP];
__device__ bf16 g_kv[BATCH * 2 * CCH * LSP];
__device__ bf16 g_o [BATCH * CCH * LSP];
__device__ bf16 g_wq [CCH * CCH];
__device__ bf16 g_wkv[2 * CCH * CCH];
__device__ bf16 g_wp [CCH * CCH];

// ---------------- PTX helpers ----------------
__device__ __forceinline__ unsigned int smem_u32(const void* p) {
    return (unsigned int)__cvta_generic_to_shared(p);
}
#define CP_ASYNC16(dst, src) \
    asm volatile("cp.async.cg.shared.global [%0], [%1], 16;\n" :: "r"(dst), "l"(src))
#define CP_COMMIT() asm volatile("cp.async.commit_group;\n" ::)
#define CP_WAIT1()  asm volatile("cp.async.wait_group 1;\n" ::)
#define CP_WAIT0()  asm volatile("cp.async.wait_group 0;\n" ::)
#define LDSM4(r0,r1,r2,r3,addr) \
    asm volatile("ldmatrix.sync.aligned.m8n8.x4.shared.b16 {%0,%1,%2,%3},[%4];" \
        : "=r"(r0),"=r"(r1),"=r"(r2),"=r"(r3) : "r"(addr))
#define LDSM4T(r0,r1,r2,r3,addr) \
    asm volatile("ldmatrix.sync.aligned.m8n8.x4.trans.shared.b16 {%0,%1,%2,%3},[%4];" \
        : "=r"(r0),"=r"(r1),"=r"(r2),"=r"(r3) : "r"(addr))
#define MMA16816(c,a,b0,b1) \
    asm volatile("mma.sync.aligned.m16n8k16.row.col.f32.bf16.bf16.f32 " \
        "{%0,%1,%2,%3},{%4,%5,%6,%7},{%8,%9},{%0,%1,%2,%3};" \
        : "+f"(c[0]),"+f"(c[1]),"+f"(c[2]),"+f"(c[3]) \
        : "r"(a[0]),"r"(a[1]),"r"(a[2]),"r"(a[3]),"r"(b0),"r"(b1))

__device__ __forceinline__ unsigned int packbf2(float a, float b) {
    bf162 t = __floats2bfloat162_rn(a, b);
    return *(unsigned int*)&t;
}

// ---------------- fp32 -> bf16 weight conversion ----------------
__global__ __launch_bounds__(256) void cvt_kernel(const float* __restrict__ src,
                                                  bf16* __restrict__ dst, int n4)
{
    int i = blockIdx.x * 256 + threadIdx.x;
    if (i < n4) {
        float4 v = ((const float4*)src)[i];
        ((bf162*)dst)[2 * i]     = __floats2bfloat162_rn(v.x, v.y);
        ((bf162*)dst)[2 * i + 1] = __floats2bfloat162_rn(v.z, v.w);
    }
}

// ---------------- GroupNorm (fp32 in, bf16 out) ----------------
__global__ __launch_bounds__(256) void gn_kernel(const float* __restrict__ x,
                                                 const float* __restrict__ w,
                                                 const float* __restrict__ bb,
                                                 bf16* __restrict__ out)
{
    int bg = blockIdx.x;
    int g  = bg & 31;
    const float4* x4 = (const float4*)(x + (size_t)bg * 16384);
    bf162*        o2 = (bf162*)(out + (size_t)bg * 16384);
    int tid = threadIdx.x;

    float s = 0.f, ss = 0.f;
    for (int i = tid; i < 4096; i += 256) {
        float4 v = x4[i];
        s  += v.x + v.y + v.z + v.w;
        ss += v.x*v.x + v.y*v.y + v.z*v.z + v.w*v.w;
    }
    __shared__ float rs[8], rss[8];
    #pragma unroll
    for (int o = 16; o; o >>= 1) {
        s  += __shfl_xor_sync(~0u, s, o);
        ss += __shfl_xor_sync(~0u, ss, o);
    }
    if ((tid & 31) == 0) { rs[tid >> 5] = s; rss[tid >> 5] = ss; }
    __syncthreads();
    if (tid < 32) {
        s  = (tid < 8) ? rs[tid]  : 0.f;
        ss = (tid < 8) ? rss[tid] : 0.f;
        #pragma unroll
        for (int o = 4; o; o >>= 1) {
            s  += __shfl_xor_sync(~0u, s, o);
            ss += __shfl_xor_sync(~0u, ss, o);
        }
        if (tid == 0) { rs[0] = s; rss[0] = ss; }
    }
    __syncthreads();
    float mean = rs[0] * (1.f / 16384.f);
    float var  = rss[0] * (1.f / 16384.f) - mean * mean;
    float inv  = rsqrtf(var + 1e-5f);

    for (int i = tid; i < 4096; i += 256) {
        int c = g * 16 + (i >> 8);
        float sc = w[c] * inv;
        float sh = bb[c] - mean * sc;
        float4 v = x4[i];
        o2[2 * i]     = __floats2bfloat162_rn(v.x * sc + sh, v.y * sc + sh);
        o2[2 * i + 1] = __floats2bfloat162_rn(v.z * sc + sh, v.w * sc + sh);
    }
}

// ---------------- conv1x1 GEMM: raw mma.sync, BK=64, 3-stage, swizzled -----
// Block 128(O) x 128(L); 8 warps = 4(m) x 2(n); warp tile 32 x 64.
// Smem: A [128 r][64 bf16=128B] 16KB/stage, B [64 r][128 bf16=256B] 16KB/stage,
// XOR swizzle (16B group ^ (row&7)); 3 stages = 96KB -> 2 CTAs/SM.
// Epilogue straight from fragments (no smem staging).
#define A_ST 16384
#define B_OFF (3 * A_ST)

template<bool BF16OUT>
__global__ __launch_bounds__(256, 2) void gemm_mma(const bf16* __restrict__ in,
                                                   const bf16* __restrict__ W,
                                                   const float* __restrict__ bias,
                                                   const float* __restrict__ resid,
                                                   void* __restrict__ outp, int O)
{
    extern __shared__ char smraw[];
    const unsigned int sbase = smem_u32(smraw);

    int b  = blockIdx.z;
    int o0 = blockIdx.y * 128;
    int l0 = blockIdx.x * 128;
    int tid = threadIdx.x, wid = tid >> 5, lane = tid & 31;
    int wm = wid >> 1, wn = wid & 1;
    int gid = lane >> 2, qtid = lane & 3;
    int lg = lane >> 3, lr = lane & 7;

    const bf16* Xb = in + (size_t)b * CCH * LSP;

    // stage chunk kc: A rows = O (128), cols = k (64); B rows = k (64), cols = L (128)
    int s_ar = tid >> 1, s_ag = tid & 1;        // A: 2 groups... (re-derived below)
    auto stage = [&](int s, int kc) {
        const bf16* Aw = W  + (size_t)o0 * CCH + kc * 64;
        const bf16* Bx = Xb + (size_t)(kc * 64) * LSP + l0;
        #pragma unroll
        for (int t = 0; t < 4; t++) {            // A: 1024 16B chunks
            int idx = tid + t * 256;
            int ar = idx >> 3, g = idx & 7;
            unsigned int dst = sbase + s * A_ST + ar * 128 + ((g ^ (ar & 7)) << 4);
            CP_ASYNC16(dst, Aw + (size_t)ar * CCH + g * 8);
        }
        #pragma unroll
        for (int t = 0; t < 4; t++) {            // B: 1024 16B chunks
            int idx = tid + t * 256;
            int br = idx >> 4, g = idx & 15;
            unsigned int dst = sbase + B_OFF + s * A_ST + br * 256 + ((g ^ (br & 7)) << 4);
            CP_ASYNC16(dst, Bx + (size_t)br * LSP + g * 8);
        }
        CP_COMMIT();
    };
    (void)s_ar; (void)s_ag;

    float acc[2][8][4] = {};   // [mi][n8 tile][frag]

    const int T = CCH / 64;    // 8 chunks
    stage(0, 0);
    stage(1, 1);

    for (int i = 0; i < T; i++) {
        int s = i % 3;
        if (i == T - 1) { CP_WAIT0(); } else { CP_WAIT1(); }
        __syncthreads();                 // chunk i ready; buffer (i+2)%3 free
        if (i + 2 < T) stage((i + 2) % 3, i + 2);

        unsigned int abase = sbase + s * A_ST;
        unsigned int bbase = sbase + B_OFF + s * A_ST;
        #pragma unroll
        for (int ks = 0; ks < 4; ks++) {
            unsigned int af[2][4];
            #pragma unroll
            for (int mi = 0; mi < 2; mi++) {
                int mrow = wm * 32 + mi * 16 + (lg & 1) * 8 + lr;
                int kg   = (ks * 16 + (lg >> 1) * 8) >> 3;
                LDSM4(af[mi][0], af[mi][1], af[mi][2], af[mi][3],
                      abase + mrow * 128 + ((kg ^ (mrow & 7)) << 4));
            }
            #pragma unroll
            for (int np = 0; np < 4; np++) {
                int krow = ks * 16 + (lg & 1) * 8 + lr;
                int ng   = (wn * 64 + np * 16 + (lg >> 1) * 8) >> 3;
                unsigned int b0, b1, b2, b3;
                LDSM4T(b0, b1, b2, b3,
                       bbase + krow * 256 + ((ng ^ (krow & 7)) << 4));
                #pragma unroll
                for (int mi = 0; mi < 2; mi++) {
                    MMA16816(acc[mi][np * 2],     af[mi], b0, b1);
                    MMA16816(acc[mi][np * 2 + 1], af[mi], b2, b3);
                }
            }
        }
    }

    // epilogue: direct from fragments. rows r0 = wm*32+mi*16+gid (+8),
    // cols c = wn*64 + t*8 + qtid*2 (pair c, c+1).
    #pragma unroll
    for (int mi = 0; mi < 2; mi++) {
        int r0 = wm * 32 + mi * 16 + gid;
        float bi0 = bias[o0 + r0];
        float bi1 = bias[o0 + r0 + 8];
        size_t row0 = ((size_t)b * O + o0 + r0) * LSP + l0;
        size_t row1 = row0 + (size_t)8 * LSP;
        #pragma unroll
        for (int t = 0; t < 8; t++) {
            int c = wn * 64 + t * 8 + qtid * 2;
            if (BF16OUT) {
                bf16* ob = (bf16*)outp;
                *(unsigned int*)&ob[row0 + c] = packbf2(acc[mi][t][0] + bi0, acc[mi][t][1] + bi0);
                *(unsigned int*)&ob[row1 + c] = packbf2(acc[mi][t][2] + bi1, acc[mi][t][3] + bi1);
            } else {
                float* of = (float*)outp;
                float2 rv0 = *(const float2*)&resid[row0 + c];
                float2 rv1 = *(const float2*)&resid[row1 + c];
                float2 v0 = {acc[mi][t][0] + bi0 + rv0.x, acc[mi][t][1] + bi0 + rv0.y};
                float2 v1 = {acc[mi][t][2] + bi1 + rv1.x, acc[mi][t][3] + bi1 + rv1.y};
                *(float2*)&of[row0 + c] = v0;
                *(float2*)&of[row1 + c] = v1;
            }
        }
    }
}

// ---------------- attention: raw mma.sync, P in registers (R5, unchanged) --
#define QI 136
#define KJ 72

__global__ __launch_bounds__(256) void attn_mma(const bf16* __restrict__ qb,
                                                const bf16* __restrict__ kvb,
                                                bf16* __restrict__ ob)
{
    __shared__ bf16 Qs[64 * QI];
    __shared__ bf16 Ks[64 * KJ];
    __shared__ bf16 Vs[64 * KJ];

    int i0 = blockIdx.x * 128;
    int h  = blockIdx.y;
    int b  = blockIdx.z;
    int tid = threadIdx.x, wid = tid >> 5, lane = tid & 31;
    int gid = lane >> 2, qtid = lane & 3;
    int ibase = wid * 16;
    int lg = lane >> 3, lr = lane & 7;

    const bf16* qp = qb  + ((size_t)b * CCH     + h * 64) * LSP;
    const bf16* kp = kvb + ((size_t)b * 2 * CCH + h * 64) * LSP;
    const bf16* vp = kvb + ((size_t)b * 2 * CCH + CCH + h * 64) * LSP;
    bf16*       op = ob  + ((size_t)b * CCH     + h * 64) * LSP;

    {
        int d = tid >> 2, c = (tid & 3) * 32;
        const uint4* s = (const uint4*)&qp[(size_t)d * LSP + i0 + c];
        uint4* t = (uint4*)&Qs[d * QI + c];
        t[0] = s[0]; t[1] = s[1]; t[2] = s[2]; t[3] = s[3];
    }
    __syncthreads();

    unsigned int qa[4][4];
    #pragma unroll
    for (int ks = 0; ks < 4; ks++) {
        int drow = ks * 16 + (lg >> 1) * 8 + lr;
        int icol = ibase + (lg & 1) * 8;
        unsigned int a = smem_u32(&Qs[drow * QI + icol]);
        LDSM4T(qa[ks][0], qa[ks][1], qa[ks][2], qa[ks][3], a);
    }

    float oacc[8][4] = {};
    float rl = 0.f, rh = 0.f;

    int dk = tid >> 2, ck = (tid & 3) * 16;
    uint4 kr0, kr1, vr0, vr1;
    {
        const uint4* ks_ = (const uint4*)&kp[(size_t)dk * LSP + ck];
        const uint4* vs_ = (const uint4*)&vp[(size_t)dk * LSP + ck];
        kr0 = ks_[0]; kr1 = ks_[1]; vr0 = vs_[0]; vr1 = vs_[1];
    }

    for (int kt = 0; kt < 16; kt++) {
        __syncthreads();
        *(uint4*)&Ks[dk * KJ + ck]     = kr0;
        *(uint4*)&Ks[dk * KJ + ck + 8] = kr1;
        *(uint4*)&Vs[dk * KJ + ck]     = vr0;
        *(uint4*)&Vs[dk * KJ + ck + 8] = vr1;
        __syncthreads();
        if (kt < 15) {
            int j0 = (kt + 1) * 64;
            const uint4* ks_ = (const uint4*)&kp[(size_t)dk * LSP + j0 + ck];
            const uint4* vs_ = (const uint4*)&vp[(size_t)dk * LSP + j0 + ck];
            kr0 = ks_[0]; kr1 = ks_[1]; vr0 = vs_[0]; vr1 = vs_[1];
        }

        float sacc[8][4] = {};
        #pragma unroll
        for (int ks = 0; ks < 4; ks++) {
            #pragma unroll
            for (int jp = 0; jp < 4; jp++) {
                int drow = ks * 16 + (lg & 1) * 8 + lr;
                int jcol = jp * 16 + (lg >> 1) * 8;
                unsigned int a = smem_u32(&Ks[drow * KJ + jcol]);
                unsigned int b0, b1, b2, b3;
                LDSM4T(b0, b1, b2, b3, a);
                MMA16816(sacc[jp * 2],     qa[ks], b0, b1);
                MMA16816(sacc[jp * 2 + 1], qa[ks], b2, b3);
            }
        }

        unsigned int pa[4][4];
        #pragma unroll
        for (int t = 0; t < 8; t++) {
            float e0 = __expf(sacc[t][0] * 0.125f);
            float e1 = __expf(sacc[t][1] * 0.125f);
            float e2 = __expf(sacc[t][2] * 0.125f);
            float e3 = __expf(sacc[t][3] * 0.125f);
            rl += e0 + e1;
            rh += e2 + e3;
            pa[t >> 1][(t & 1) * 2]     = packbf2(e0, e1);
            pa[t >> 1][(t & 1) * 2 + 1] = packbf2(e2, e3);
        }

        #pragma unroll
        for (int ks = 0; ks < 4; ks++) {
            #pragma unroll
            for (int dp = 0; dp < 4; dp++) {
                int drow = dp * 16 + (lg >> 1) * 8 + lr;
                int jcol = ks * 16 + (lg & 1) * 8;
                unsigned int a = smem_u32(&Vs[drow * KJ + jcol]);
                unsigned int b0, b1, b2, b3;
                LDSM4(b0, b1, b2, b3, a);
                MMA16816(oacc[dp * 2],     pa[ks], b0, b1);
                MMA16816(oacc[dp * 2 + 1], pa[ks], b2, b3);
            }
        }
    }

    rl += __shfl_xor_sync(~0u, rl, 1); rl += __shfl_xor_sync(~0u, rl, 2);
    rh += __shfl_xor_sync(~0u, rh, 1); rh += __shfl_xor_sync(~0u, rh, 2);
    float il = 1.f / rl, ih = 1.f / rh;

    #pragma unroll
    for (int t = 0; t < 8; t++) {
        int dcol = t * 8 + qtid * 2;
        Qs[dcol * QI + ibase + gid]           = __float2bfloat16(oacc[t][0] * il);
        Qs[(dcol + 1) * QI + ibase + gid]     = __float2bfloat16(oacc[t][1] * il);
        Qs[dcol * QI + ibase + gid + 8]       = __float2bfloat16(oacc[t][2] * ih);
        Qs[(dcol + 1) * QI + ibase + gid + 8] = __float2bfloat16(oacc[t][3] * ih);
    }
    __syncthreads();

    {
        int d = tid >> 2, c = (tid & 3) * 32;
        const uint4* s = (const uint4*)&Qs[d * QI + c];
        uint4* t = (uint4*)&op[(size_t)d * LSP + i0 + c];
        t[0] = s[0]; t[1] = s[1]; t[2] = s[2]; t[3] = s[3];
    }
}

// ---------------- launch ----------------
extern "C" void kernel_launch(void* const* d_in, const int* in_sizes, int n_in,
                              void* d_out, int out_size)
{
    const float* x   = (const float*)d_in[0];
    const float* ctx = (const float*)d_in[1];
    const float* nqw = (const float*)d_in[2];
    const float* nqb = (const float*)d_in[3];
    const float* nkw = (const float*)d_in[4];
    const float* nkb = (const float*)d_in[5];
    const float* cqw = (const float*)d_in[6];
    const float* cqb = (const float*)d_in[7];
    const float* ckw = (const float*)d_in[8];
    const float* ckb = (const float*)d_in[9];
    const float* pw  = (const float*)d_in[10];
    const float* pb  = (const float*)d_in[11];
    float* out = (float*)d_out;

    bf16 *xn, *cn, *q, *kv, *o, *wq, *wkv, *wp;
    cudaGetSymbolAddress((void**)&xn,  g_xn);
    cudaGetSymbolAddress((void**)&cn,  g_cn);
    cudaGetSymbolAddress((void**)&q,   g_q);
    cudaGetSymbolAddress((void**)&kv,  g_kv);
    cudaGetSymbolAddress((void**)&o,   g_o);
    cudaGetSymbolAddress((void**)&wq,  g_wq);
    cudaGetSymbolAddress((void**)&wkv, g_wkv);
    cudaGetSymbolAddress((void**)&wp,  g_wp);

    const int gsmem = 6 * A_ST;   // 98304 B (3 stages x (A 16KB + B 16KB))
    cudaFuncSetAttribute(gemm_mma<true>,  cudaFuncAttributeMaxDynamicSharedMemorySize, gsmem);
    cudaFuncSetAttribute(gemm_mma<false>, cudaFuncAttributeMaxDynamicSharedMemorySize, gsmem);

    cvt_kernel<<<CCH * CCH / 1024, 256>>>(cqw, wq,  CCH * CCH / 4);
    cvt_kernel<<<2 * CCH * CCH / 1024, 256>>>(ckw, wkv, 2 * CCH * CCH / 4);
    cvt_kernel<<<CCH * CCH / 1024, 256>>>(pw,  wp,  CCH * CCH / 4);

    gn_kernel<<<BATCH * 32, 256>>>(x,   nqw, nqb, xn);
    gn_kernel<<<BATCH * 32, 256>>>(ctx, nkw, nkb, cn);

    gemm_mma<true><<<dim3(8, 4, BATCH), 256, gsmem>>>(xn, wq,  cqb, nullptr, q,  CCH);
    gemm_mma<true><<<dim3(8, 8, BATCH), 256, gsmem>>>(cn, wkv, ckb, nullptr, kv, 2 * CCH);

    attn_mma<<<dim3(8, NHEADS, BATCH), 256>>>(q, kv, o);

    gemm_mma<false><<<dim3(8, 4, BATCH), 256, gsmem>>>(o, wp, pb, x, out, CCH);
}

// round 10
// speedup vs baseline: 1.4294x; 1.0759x over previous
#include <cuda_runtime.h>
#include <cuda_bf16.h>
#include <math.h>
#include <cstdint>

#define BATCH  16
#define CCH    512
#define LSP    1024
#define NHEADS 8

typedef __nv_bfloat16 bf16;
typedef __nv_bfloat162 bf162;

// ---------------- scratch (static device globals; no allocs) ----------------
__device__ bf16 g_xn[BATCH * CCH * LSP];
__device__ bf16 g_cn[BATCH * CCH * LSP];
__device__ bf16 g_q [BATCH * CCH * LSP];
__device__ bf16 g_kv[BATCH * 2 * CCH * LSP];
__device__ bf16 g_o [BATCH * CCH * LSP];
__device__ bf16 g_wq [CCH * CCH];
__device__ bf16 g_wkv[2 * CCH * CCH];
__device__ bf16 g_wp [CCH * CCH];

// ---------------- PTX helpers ----------------
__device__ __forceinline__ unsigned int smem_u32(const void* p) {
    return (unsigned int)__cvta_generic_to_shared(p);
}
#define CP_ASYNC16(dst, src) \
    asm volatile("cp.async.cg.shared.global [%0], [%1], 16;\n" :: "r"(dst), "l"(src))
#define CP_COMMIT() asm volatile("cp.async.commit_group;\n" ::)
#define CP_WAIT1()  asm volatile("cp.async.wait_group 1;\n" ::)
#define CP_WAIT0()  asm volatile("cp.async.wait_group 0;\n" ::)
#define LDSM4(r0,r1,r2,r3,addr) \
    asm volatile("ldmatrix.sync.aligned.m8n8.x4.shared.b16 {%0,%1,%2,%3},[%4];" \
        : "=r"(r0),"=r"(r1),"=r"(r2),"=r"(r3) : "r"(addr))
#define LDSM4T(r0,r1,r2,r3,addr) \
    asm volatile("ldmatrix.sync.aligned.m8n8.x4.trans.shared.b16 {%0,%1,%2,%3},[%4];" \
        : "=r"(r0),"=r"(r1),"=r"(r2),"=r"(r3) : "r"(addr))
#define MMA16816(c,a,b0,b1) \
    asm volatile("mma.sync.aligned.m16n8k16.row.col.f32.bf16.bf16.f32 " \
        "{%0,%1,%2,%3},{%4,%5,%6,%7},{%8,%9},{%0,%1,%2,%3};" \
        : "+f"(c[0]),"+f"(c[1]),"+f"(c[2]),"+f"(c[3]) \
        : "r"(a[0]),"r"(a[1]),"r"(a[2]),"r"(a[3]),"r"(b0),"r"(b1))

__device__ __forceinline__ unsigned int packbf2(float a, float b) {
    bf162 t = __floats2bfloat162_rn(a, b);
    return *(unsigned int*)&t;
}

// ---------------- fp32 -> bf16 weight conversion (all 3 weights, 1 launch) --
__global__ __launch_bounds__(256) void cvt_all(const float* __restrict__ s0, bf16* d0, int n0,
                                               const float* __restrict__ s1, bf16* d1, int n1,
                                               const float* __restrict__ s2, bf16* d2, int n2)
{
    int i = blockIdx.x * 256 + threadIdx.x;
    const float* src; bf16* dst;
    if (i < n0)           { src = s0; dst = d0; }
    else if (i < n0 + n1) { i -= n0; src = s1; dst = d1; }
    else if (i < n0 + n1 + n2) { i -= n0 + n1; src = s2; dst = d2; }
    else return;
    float4 v = ((const float4*)src)[i];
    ((bf162*)dst)[2 * i]     = __floats2bfloat162_rn(v.x, v.y);
    ((bf162*)dst)[2 * i + 1] = __floats2bfloat162_rn(v.z, v.w);
}

// ---------------- GroupNorm (both tensors, 1 launch) ----------------
__global__ __launch_bounds__(256) void gn_kernel(const float* __restrict__ x0,
                                                 const float* __restrict__ w0,
                                                 const float* __restrict__ b0,
                                                 bf16* __restrict__ out0,
                                                 const float* __restrict__ x1,
                                                 const float* __restrict__ w1,
                                                 const float* __restrict__ b1,
                                                 bf16* __restrict__ out1)
{
    int bg = blockIdx.x;
    const float* x; const float* w; const float* bb; bf16* out;
    if (bg < BATCH * 32) { x = x0; w = w0; bb = b0; out = out0; }
    else { bg -= BATCH * 32; x = x1; w = w1; bb = b1; out = out1; }
    int g = bg & 31;
    const float4* x4 = (const float4*)(x + (size_t)bg * 16384);
    bf162*        o2 = (bf162*)(out + (size_t)bg * 16384);
    int tid = threadIdx.x;

    float s = 0.f, ss = 0.f;
    for (int i = tid; i < 4096; i += 256) {
        float4 v = x4[i];
        s  += v.x + v.y + v.z + v.w;
        ss += v.x*v.x + v.y*v.y + v.z*v.z + v.w*v.w;
    }
    __shared__ float rs[8], rss[8];
    #pragma unroll
    for (int o = 16; o; o >>= 1) {
        s  += __shfl_xor_sync(~0u, s, o);
        ss += __shfl_xor_sync(~0u, ss, o);
    }
    if ((tid & 31) == 0) { rs[tid >> 5] = s; rss[tid >> 5] = ss; }
    __syncthreads();
    if (tid < 32) {
        s  = (tid < 8) ? rs[tid]  : 0.f;
        ss = (tid < 8) ? rss[tid] : 0.f;
        #pragma unroll
        for (int o = 4; o; o >>= 1) {
            s  += __shfl_xor_sync(~0u, s, o);
            ss += __shfl_xor_sync(~0u, ss, o);
        }
        if (tid == 0) { rs[0] = s; rss[0] = ss; }
    }
    __syncthreads();
    float mean = rs[0] * (1.f / 16384.f);
    float var  = rss[0] * (1.f / 16384.f) - mean * mean;
    float inv  = rsqrtf(var + 1e-5f);

    for (int i = tid; i < 4096; i += 256) {
        int c = g * 16 + (i >> 8);
        float sc = w[c] * inv;
        float sh = bb[c] - mean * sc;
        float4 v = x4[i];
        o2[2 * i]     = __floats2bfloat162_rn(v.x * sc + sh, v.y * sc + sh);
        o2[2 * i + 1] = __floats2bfloat162_rn(v.z * sc + sh, v.w * sc + sh);
    }
}

// ---------------- conv1x1 GEMM (R9 winner, unchanged) ----------------
#define A_ST 16384
#define B_OFF (3 * A_ST)

template<bool BF16OUT>
__global__ __launch_bounds__(256, 2) void gemm_mma(const bf16* __restrict__ in,
                                                   const bf16* __restrict__ W,
                                                   const float* __restrict__ bias,
                                                   const float* __restrict__ resid,
                                                   void* __restrict__ outp, int O)
{
    extern __shared__ char smraw[];
    const unsigned int sbase = smem_u32(smraw);

    int b  = blockIdx.z;
    int o0 = blockIdx.y * 128;
    int l0 = blockIdx.x * 128;
    int tid = threadIdx.x, wid = tid >> 5, lane = tid & 31;
    int wm = wid >> 1, wn = wid & 1;
    int gid = lane >> 2, qtid = lane & 3;
    int lg = lane >> 3, lr = lane & 7;

    const bf16* Xb = in + (size_t)b * CCH * LSP;

    auto stage = [&](int s, int kc) {
        const bf16* Aw = W  + (size_t)o0 * CCH + kc * 64;
        const bf16* Bx = Xb + (size_t)(kc * 64) * LSP + l0;
        #pragma unroll
        for (int t = 0; t < 4; t++) {
            int idx = tid + t * 256;
            int ar = idx >> 3, g = idx & 7;
            unsigned int dst = sbase + s * A_ST + ar * 128 + ((g ^ (ar & 7)) << 4);
            CP_ASYNC16(dst, Aw + (size_t)ar * CCH + g * 8);
        }
        #pragma unroll
        for (int t = 0; t < 4; t++) {
            int idx = tid + t * 256;
            int br = idx >> 4, g = idx & 15;
            unsigned int dst = sbase + B_OFF + s * A_ST + br * 256 + ((g ^ (br & 7)) << 4);
            CP_ASYNC16(dst, Bx + (size_t)br * LSP + g * 8);
        }
        CP_COMMIT();
    };

    float acc[2][8][4] = {};

    const int T = CCH / 64;
    stage(0, 0);
    stage(1, 1);

    for (int i = 0; i < T; i++) {
        int s = i % 3;
        if (i == T - 1) { CP_WAIT0(); } else { CP_WAIT1(); }
        __syncthreads();
        if (i + 2 < T) stage((i + 2) % 3, i + 2);

        unsigned int abase = sbase + s * A_ST;
        unsigned int bbase = sbase + B_OFF + s * A_ST;
        #pragma unroll
        for (int ks = 0; ks < 4; ks++) {
            unsigned int af[2][4];
            #pragma unroll
            for (int mi = 0; mi < 2; mi++) {
                int mrow = wm * 32 + mi * 16 + (lg & 1) * 8 + lr;
                int kg   = (ks * 16 + (lg >> 1) * 8) >> 3;
                LDSM4(af[mi][0], af[mi][1], af[mi][2], af[mi][3],
                      abase + mrow * 128 + ((kg ^ (mrow & 7)) << 4));
            }
            #pragma unroll
            for (int np = 0; np < 4; np++) {
                int krow = ks * 16 + (lg & 1) * 8 + lr;
                int ng   = (wn * 64 + np * 16 + (lg >> 1) * 8) >> 3;
                unsigned int b0, b1, b2, b3;
                LDSM4T(b0, b1, b2, b3,
                       bbase + krow * 256 + ((ng ^ (krow & 7)) << 4));
                #pragma unroll
                for (int mi = 0; mi < 2; mi++) {
                    MMA16816(acc[mi][np * 2],     af[mi], b0, b1);
                    MMA16816(acc[mi][np * 2 + 1], af[mi], b2, b3);
                }
            }
        }
    }

    #pragma unroll
    for (int mi = 0; mi < 2; mi++) {
        int r0 = wm * 32 + mi * 16 + gid;
        float bi0 = bias[o0 + r0];
        float bi1 = bias[o0 + r0 + 8];
        size_t row0 = ((size_t)b * O + o0 + r0) * LSP + l0;
        size_t row1 = row0 + (size_t)8 * LSP;
        #pragma unroll
        for (int t = 0; t < 8; t++) {
            int c = wn * 64 + t * 8 + qtid * 2;
            if (BF16OUT) {
                bf16* ob = (bf16*)outp;
                *(unsigned int*)&ob[row0 + c] = packbf2(acc[mi][t][0] + bi0, acc[mi][t][1] + bi0);
                *(unsigned int*)&ob[row1 + c] = packbf2(acc[mi][t][2] + bi1, acc[mi][t][3] + bi1);
            } else {
                float* of = (float*)outp;
                float2 rv0 = *(const float2*)&resid[row0 + c];
                float2 rv1 = *(const float2*)&resid[row1 + c];
                float2 v0 = {acc[mi][t][0] + bi0 + rv0.x, acc[mi][t][1] + bi0 + rv0.y};
                float2 v1 = {acc[mi][t][2] + bi1 + rv1.x, acc[mi][t][3] + bi1 + rv1.y};
                *(float2*)&of[row0 + c] = v0;
                *(float2*)&of[row1 + c] = v1;
            }
        }
    }
}

// ---------------- attention: 2-stage cp.async K/V, 1 sync/iter ----------------
// Smem: Qs [64][QI], K/V double-buffered [64][KJ] each. 54272 B dynamic.
#define QI 136
#define KJ 72
#define Q_BYTES (64 * QI * 2)       // 17408
#define KV_BYTES (64 * KJ * 2)      // 9216
#define ATTN_SMEM (Q_BYTES + 4 * KV_BYTES)   // 54272

__global__ __launch_bounds__(256, 2) void attn_mma(const bf16* __restrict__ qb,
                                                   const bf16* __restrict__ kvb,
                                                   bf16* __restrict__ ob)
{
    extern __shared__ char asmraw[];
    bf16* Qs = (bf16*)asmraw;
    const unsigned int sb = smem_u32(asmraw);
    const unsigned int kbuf0 = sb + Q_BYTES;
    const unsigned int vbuf0 = sb + Q_BYTES + 2 * KV_BYTES;

    int i0 = blockIdx.x * 128;
    int h  = blockIdx.y;
    int b  = blockIdx.z;
    int tid = threadIdx.x, wid = tid >> 5, lane = tid & 31;
    int gid = lane >> 2, qtid = lane & 3;
    int ibase = wid * 16;
    int lg = lane >> 3, lr = lane & 7;

    const bf16* qp = qb  + ((size_t)b * CCH     + h * 64) * LSP;
    const bf16* kp = kvb + ((size_t)b * 2 * CCH + h * 64) * LSP;
    const bf16* vp = kvb + ((size_t)b * 2 * CCH + CCH + h * 64) * LSP;
    bf16*       op = ob  + ((size_t)b * CCH     + h * 64) * LSP;

    int dk = tid >> 2, ck4 = (tid & 3);   // row dk, 16 bf16 at ck4*16

    // stage K/V tile kt into buffer s (cp.async, 4x16B per thread)
    auto stageKV = [&](int s, int kt) {
        const bf16* ks_ = kp + (size_t)dk * LSP + kt * 64 + ck4 * 16;
        const bf16* vs_ = vp + (size_t)dk * LSP + kt * 64 + ck4 * 16;
        unsigned int ko = kbuf0 + s * KV_BYTES + dk * (KJ * 2) + ck4 * 32;
        unsigned int vo = vbuf0 + s * KV_BYTES + dk * (KJ * 2) + ck4 * 32;
        CP_ASYNC16(ko,      ks_);
        CP_ASYNC16(ko + 16, ks_ + 8);
        CP_ASYNC16(vo,      vs_);
        CP_ASYNC16(vo + 16, vs_ + 8);
        CP_COMMIT();
    };

    stageKV(0, 0);

    // load Q tile
    {
        int d = tid >> 2, c = (tid & 3) * 32;
        const uint4* s = (const uint4*)&qp[(size_t)d * LSP + i0 + c];
        uint4* t = (uint4*)&Qs[d * QI + c];
        t[0] = s[0]; t[1] = s[1]; t[2] = s[2]; t[3] = s[3];
    }
    __syncthreads();

    unsigned int qa[4][4];
    #pragma unroll
    for (int ks = 0; ks < 4; ks++) {
        int drow = ks * 16 + (lg >> 1) * 8 + lr;
        int icol = ibase + (lg & 1) * 8;
        unsigned int a = smem_u32(&Qs[drow * QI + icol]);
        LDSM4T(qa[ks][0], qa[ks][1], qa[ks][2], qa[ks][3], a);
    }

    float oacc[8][4] = {};
    float rl = 0.f, rh = 0.f;

    for (int kt = 0; kt < 16; kt++) {
        int s = kt & 1;
        CP_WAIT0();
        __syncthreads();    // tile kt visible; all warps done computing kt-1 (buffer s^1 free)
        if (kt < 15) stageKV(s ^ 1, kt + 1);

        unsigned int kb = kbuf0 + s * KV_BYTES;
        unsigned int vb = vbuf0 + s * KV_BYTES;

        float sacc[8][4] = {};
        #pragma unroll
        for (int ks = 0; ks < 4; ks++) {
            #pragma unroll
            for (int jp = 0; jp < 4; jp++) {
                int drow = ks * 16 + (lg & 1) * 8 + lr;
                int jcol = jp * 16 + (lg >> 1) * 8;
                unsigned int a = kb + drow * (KJ * 2) + jcol * 2;
                unsigned int b0, b1, b2, b3;
                LDSM4T(b0, b1, b2, b3, a);
                MMA16816(sacc[jp * 2],     qa[ks], b0, b1);
                MMA16816(sacc[jp * 2 + 1], qa[ks], b2, b3);
            }
        }

        unsigned int pa[4][4];
        #pragma unroll
        for (int t = 0; t < 8; t++) {
            float e0 = __expf(sacc[t][0] * 0.125f);
            float e1 = __expf(sacc[t][1] * 0.125f);
            float e2 = __expf(sacc[t][2] * 0.125f);
            float e3 = __expf(sacc[t][3] * 0.125f);
            rl += e0 + e1;
            rh += e2 + e3;
            pa[t >> 1][(t & 1) * 2]     = packbf2(e0, e1);
            pa[t >> 1][(t & 1) * 2 + 1] = packbf2(e2, e3);
        }

        #pragma unroll
        for (int ks = 0; ks < 4; ks++) {
            #pragma unroll
            for (int dp = 0; dp < 4; dp++) {
                int drow = dp * 16 + (lg >> 1) * 8 + lr;
                int jcol = ks * 16 + (lg & 1) * 8;
                unsigned int a = vb + drow * (KJ * 2) + jcol * 2;
                unsigned int b0, b1, b2, b3;
                LDSM4(b0, b1, b2, b3, a);
                MMA16816(oacc[dp * 2],     pa[ks], b0, b1);
                MMA16816(oacc[dp * 2 + 1], pa[ks], b2, b3);
            }
        }
    }

    rl += __shfl_xor_sync(~0u, rl, 1); rl += __shfl_xor_sync(~0u, rl, 2);
    rh += __shfl_xor_sync(~0u, rh, 1); rh += __shfl_xor_sync(~0u, rh, 2);
    float il = 1.f / rl, ih = 1.f / rh;

    __syncthreads();   // done with Qs reads (qa cached in regs since prologue)
    #pragma unroll
    for (int t = 0; t < 8; t++) {
        int dcol = t * 8 + qtid * 2;
        Qs[dcol * QI + ibase + gid]           = __float2bfloat16(oacc[t][0] * il);
        Qs[(dcol + 1) * QI + ibase + gid]     = __float2bfloat16(oacc[t][1] * il);
        Qs[dcol * QI + ibase + gid + 8]       = __float2bfloat16(oacc[t][2] * ih);
        Qs[(dcol + 1) * QI + ibase + gid + 8] = __float2bfloat16(oacc[t][3] * ih);
    }
    __syncthreads();

    {
        int d = tid >> 2, c = (tid & 3) * 32;
        const uint4* s = (const uint4*)&Qs[d * QI + c];
        uint4* t = (uint4*)&op[(size_t)d * LSP + i0 + c];
        t[0] = s[0]; t[1] = s[1]; t[2] = s[2]; t[3] = s[3];
    }
}

// ---------------- launch ----------------
extern "C" void kernel_launch(void* const* d_in, const int* in_sizes, int n_in,
                              void* d_out, int out_size)
{
    const float* x   = (const float*)d_in[0];
    const float* ctx = (const float*)d_in[1];
    const float* nqw = (const float*)d_in[2];
    const float* nqb = (const float*)d_in[3];
    const float* nkw = (const float*)d_in[4];
    const float* nkb = (const float*)d_in[5];
    const float* cqw = (const float*)d_in[6];
    const float* cqb = (const float*)d_in[7];
    const float* ckw = (const float*)d_in[8];
    const float* ckb = (const float*)d_in[9];
    const float* pw  = (const float*)d_in[10];
    const float* pb  = (const float*)d_in[11];
    float* out = (float*)d_out;

    bf16 *xn, *cn, *q, *kv, *o, *wq, *wkv, *wp;
    cudaGetSymbolAddress((void**)&xn,  g_xn);
    cudaGetSymbolAddress((void**)&cn,  g_cn);
    cudaGetSymbolAddress((void**)&q,   g_q);
    cudaGetSymbolAddress((void**)&kv,  g_kv);
    cudaGetSymbolAddress((void**)&o,   g_o);
    cudaGetSymbolAddress((void**)&wq,  g_wq);
    cudaGetSymbolAddress((void**)&wkv, g_wkv);
    cudaGetSymbolAddress((void**)&wp,  g_wp);

    const int gsmem = 6 * A_ST;   // 98304 B
    cudaFuncSetAttribute(gemm_mma<true>,  cudaFuncAttributeMaxDynamicSharedMemorySize, gsmem);
    cudaFuncSetAttribute(gemm_mma<false>, cudaFuncAttributeMaxDynamicSharedMemorySize, gsmem);
    cudaFuncSetAttribute(attn_mma, cudaFuncAttributeMaxDynamicSharedMemorySize, ATTN_SMEM);

    const int nq = CCH * CCH / 4, nkv = 2 * CCH * CCH / 4;
    cvt_all<<<(nq + nkv + nq + 255) / 256, 256>>>(cqw, wq, nq, ckw, wkv, nkv, pw, wp, nq);

    gn_kernel<<<2 * BATCH * 32, 256>>>(x, nqw, nqb, xn, ctx, nkw, nkb, cn);

    gemm_mma<true><<<dim3(8, 4, BATCH), 256, gsmem>>>(xn, wq,  cqb, nullptr, q,  CCH);
    gemm_mma<true><<<dim3(8, 8, BATCH), 256, gsmem>>>(cn, wkv, ckb, nullptr, kv, 2 * CCH);

    attn_mma<<<dim3(8, NHEADS, BATCH), 256, ATTN_SMEM>>>(q, kv, o);

    gemm_mma<false><<<dim3(8, 4, BATCH), 256, gsmem>>>(o, wp, pb, x, out, CCH);
}

// round 11
// speedup vs baseline: 1.4826x; 1.0372x over previous
#include <cuda_runtime.h>
#include <cuda_bf16.h>
#include <math.h>
#include <cstdint>

#define BATCH  16
#define CCH    512
#define LSP    1024
#define NHEADS 8

typedef __nv_bfloat16 bf16;
typedef __nv_bfloat162 bf162;

// ---------------- scratch (static device globals; no allocs) ----------------
__device__ bf16 g_xn[BATCH * CCH * LSP];
__device__ bf16 g_cn[BATCH * CCH * LSP];
__device__ bf16 g_q [BATCH * CCH * LSP];
__device__ bf16 g_kv[BATCH * 2 * CCH * LSP];
__device__ bf16 g_o [BATCH * CCH * LSP];
__device__ bf16 g_wq [CCH * CCH];
__device__ bf16 g_wkv[2 * CCH * CCH];
__device__ bf16 g_wp [CCH * CCH];

// ---------------- PTX helpers ----------------
__device__ __forceinline__ unsigned int smem_u32(const void* p) {
    return (unsigned int)__cvta_generic_to_shared(p);
}
#define CP_ASYNC16(dst, src) \
    asm volatile("cp.async.cg.shared.global [%0], [%1], 16;\n" :: "r"(dst), "l"(src))
#define CP_COMMIT() asm volatile("cp.async.commit_group;\n" ::)
#define CP_WAIT1()  asm volatile("cp.async.wait_group 1;\n" ::)
#define CP_WAIT0()  asm volatile("cp.async.wait_group 0;\n" ::)
#define LDSM4(r0,r1,r2,r3,addr) \
    asm volatile("ldmatrix.sync.aligned.m8n8.x4.shared.b16 {%0,%1,%2,%3},[%4];" \
        : "=r"(r0),"=r"(r1),"=r"(r2),"=r"(r3) : "r"(addr))
#define LDSM4T(r0,r1,r2,r3,addr) \
    asm volatile("ldmatrix.sync.aligned.m8n8.x4.trans.shared.b16 {%0,%1,%2,%3},[%4];" \
        : "=r"(r0),"=r"(r1),"=r"(r2),"=r"(r3) : "r"(addr))
#define MMA16816(c,a,b0,b1) \
    asm volatile("mma.sync.aligned.m16n8k16.row.col.f32.bf16.bf16.f32 " \
        "{%0,%1,%2,%3},{%4,%5,%6,%7},{%8,%9},{%0,%1,%2,%3};" \
        : "+f"(c[0]),"+f"(c[1]),"+f"(c[2]),"+f"(c[3]) \
        : "r"(a[0]),"r"(a[1]),"r"(a[2]),"r"(a[3]),"r"(b0),"r"(b1))

__device__ __forceinline__ unsigned int packbf2(float a, float b) {
    bf162 t = __floats2bfloat162_rn(a, b);
    return *(unsigned int*)&t;
}

// ---------------- head kernel: GroupNorm (1024 blocks) + weight cvt (1024) --
__global__ __launch_bounds__(256) void head_kernel(
    const float* __restrict__ x0, const float* __restrict__ w0,
    const float* __restrict__ b0, bf16* __restrict__ out0,
    const float* __restrict__ x1, const float* __restrict__ w1,
    const float* __restrict__ b1, bf16* __restrict__ out1,
    const float* __restrict__ cs0, bf16* cd0, int n0,
    const float* __restrict__ cs1, bf16* cd1, int n1,
    const float* __restrict__ cs2, bf16* cd2, int n2)
{
    int bg = blockIdx.x;
    int tid = threadIdx.x;

    if (bg >= 2 * BATCH * 32) {
        // weight conversion blocks
        int i = (bg - 2 * BATCH * 32) * 256 + tid;
        const float* src; bf16* dst;
        if (i < n0)                { src = cs0; dst = cd0; }
        else if (i < n0 + n1)      { i -= n0; src = cs1; dst = cd1; }
        else if (i < n0 + n1 + n2) { i -= n0 + n1; src = cs2; dst = cd2; }
        else return;
        float4 v = ((const float4*)src)[i];
        ((bf162*)dst)[2 * i]     = __floats2bfloat162_rn(v.x, v.y);
        ((bf162*)dst)[2 * i + 1] = __floats2bfloat162_rn(v.z, v.w);
        return;
    }

    const float* x; const float* w; const float* bb; bf16* out;
    if (bg < BATCH * 32) { x = x0; w = w0; bb = b0; out = out0; }
    else { bg -= BATCH * 32; x = x1; w = w1; bb = b1; out = out1; }
    int g = bg & 31;
    const float4* x4 = (const float4*)(x + (size_t)bg * 16384);
    bf162*        o2 = (bf162*)(out + (size_t)bg * 16384);

    float s = 0.f, ss = 0.f;
    for (int i = tid; i < 4096; i += 256) {
        float4 v = x4[i];
        s  += v.x + v.y + v.z + v.w;
        ss += v.x*v.x + v.y*v.y + v.z*v.z + v.w*v.w;
    }
    __shared__ float rs[8], rss[8];
    #pragma unroll
    for (int o = 16; o; o >>= 1) {
        s  += __shfl_xor_sync(~0u, s, o);
        ss += __shfl_xor_sync(~0u, ss, o);
    }
    if ((tid & 31) == 0) { rs[tid >> 5] = s; rss[tid >> 5] = ss; }
    __syncthreads();
    if (tid < 32) {
        s  = (tid < 8) ? rs[tid]  : 0.f;
        ss = (tid < 8) ? rss[tid] : 0.f;
        #pragma unroll
        for (int o = 4; o; o >>= 1) {
            s  += __shfl_xor_sync(~0u, s, o);
            ss += __shfl_xor_sync(~0u, ss, o);
        }
        if (tid == 0) { rs[0] = s; rss[0] = ss; }
    }
    __syncthreads();
    float mean = rs[0] * (1.f / 16384.f);
    float var  = rss[0] * (1.f / 16384.f) - mean * mean;
    float inv  = rsqrtf(var + 1e-5f);

    for (int i = tid; i < 4096; i += 256) {
        int c = g * 16 + (i >> 8);
        float sc = w[c] * inv;
        float sh = bb[c] - mean * sc;
        float4 v = x4[i];
        o2[2 * i]     = __floats2bfloat162_rn(v.x * sc + sh, v.y * sc + sh);
        o2[2 * i + 1] = __floats2bfloat162_rn(v.z * sc + sh, v.w * sc + sh);
    }
}

// ---------------- conv1x1 GEMM core (R9 winner) ----------------
#define A_ST 16384
#define B_OFF (3 * A_ST)

template<bool BF16OUT>
__device__ __forceinline__ void gemm_body(const bf16* __restrict__ in,
                                          const bf16* __restrict__ W,
                                          const float* __restrict__ bias,
                                          const float* __restrict__ resid,
                                          void* __restrict__ outp, int O,
                                          int b, int o0, int l0, char* smraw)
{
    const unsigned int sbase = smem_u32(smraw);
    int tid = threadIdx.x, wid = tid >> 5, lane = tid & 31;
    int wm = wid >> 1, wn = wid & 1;
    int gid = lane >> 2, qtid = lane & 3;
    int lg = lane >> 3, lr = lane & 7;

    const bf16* Xb = in + (size_t)b * CCH * LSP;

    auto stage = [&](int s, int kc) {
        const bf16* Aw = W  + (size_t)o0 * CCH + kc * 64;
        const bf16* Bx = Xb + (size_t)(kc * 64) * LSP + l0;
        #pragma unroll
        for (int t = 0; t < 4; t++) {
            int idx = tid + t * 256;
            int ar = idx >> 3, g = idx & 7;
            unsigned int dst = sbase + s * A_ST + ar * 128 + ((g ^ (ar & 7)) << 4);
            CP_ASYNC16(dst, Aw + (size_t)ar * CCH + g * 8);
        }
        #pragma unroll
        for (int t = 0; t < 4; t++) {
            int idx = tid + t * 256;
            int br = idx >> 4, g = idx & 15;
            unsigned int dst = sbase + B_OFF + s * A_ST + br * 256 + ((g ^ (br & 7)) << 4);
            CP_ASYNC16(dst, Bx + (size_t)br * LSP + g * 8);
        }
        CP_COMMIT();
    };

    float acc[2][8][4] = {};

    const int T = CCH / 64;
    stage(0, 0);
    stage(1, 1);

    for (int i = 0; i < T; i++) {
        int s = i % 3;
        if (i == T - 1) { CP_WAIT0(); } else { CP_WAIT1(); }
        __syncthreads();
        if (i + 2 < T) stage((i + 2) % 3, i + 2);

        unsigned int abase = sbase + s * A_ST;
        unsigned int bbase = sbase + B_OFF + s * A_ST;
        #pragma unroll
        for (int ks = 0; ks < 4; ks++) {
            unsigned int af[2][4];
            #pragma unroll
            for (int mi = 0; mi < 2; mi++) {
                int mrow = wm * 32 + mi * 16 + (lg & 1) * 8 + lr;
                int kg   = (ks * 16 + (lg >> 1) * 8) >> 3;
                LDSM4(af[mi][0], af[mi][1], af[mi][2], af[mi][3],
                      abase + mrow * 128 + ((kg ^ (mrow & 7)) << 4));
            }
            #pragma unroll
            for (int np = 0; np < 4; np++) {
                int krow = ks * 16 + (lg & 1) * 8 + lr;
                int ng   = (wn * 64 + np * 16 + (lg >> 1) * 8) >> 3;
                unsigned int b0, b1, b2, b3;
                LDSM4T(b0, b1, b2, b3,
                       bbase + krow * 256 + ((ng ^ (krow & 7)) << 4));
                #pragma unroll
                for (int mi = 0; mi < 2; mi++) {
                    MMA16816(acc[mi][np * 2],     af[mi], b0, b1);
                    MMA16816(acc[mi][np * 2 + 1], af[mi], b2, b3);
                }
            }
        }
    }

    #pragma unroll
    for (int mi = 0; mi < 2; mi++) {
        int r0 = wm * 32 + mi * 16 + gid;
        float bi0 = bias[o0 + r0];
        float bi1 = bias[o0 + r0 + 8];
        size_t row0 = ((size_t)b * O + o0 + r0) * LSP + l0;
        size_t row1 = row0 + (size_t)8 * LSP;
        #pragma unroll
        for (int t = 0; t < 8; t++) {
            int c = wn * 64 + t * 8 + qtid * 2;
            if (BF16OUT) {
                bf16* ob = (bf16*)outp;
                *(unsigned int*)&ob[row0 + c] = packbf2(acc[mi][t][0] + bi0, acc[mi][t][1] + bi0);
                *(unsigned int*)&ob[row1 + c] = packbf2(acc[mi][t][2] + bi1, acc[mi][t][3] + bi1);
            } else {
                float* of = (float*)outp;
                float2 rv0 = *(const float2*)&resid[row0 + c];
                float2 rv1 = *(const float2*)&resid[row1 + c];
                float2 v0 = {acc[mi][t][0] + bi0 + rv0.x, acc[mi][t][1] + bi0 + rv0.y};
                float2 v1 = {acc[mi][t][2] + bi1 + rv1.x, acc[mi][t][3] + bi1 + rv1.y};
                *(float2*)&of[row0 + c] = v0;
                *(float2*)&of[row1 + c] = v1;
            }
        }
    }
}

// merged q + kv GEMM: y in [0,4) -> q from xn; y in [4,12) -> kv from cn
__global__ __launch_bounds__(256, 2) void gemm_qkv(const bf16* __restrict__ xn,
                                                   const bf16* __restrict__ cn,
                                                   const bf16* __restrict__ wq,
                                                   const bf16* __restrict__ wkv,
                                                   const float* __restrict__ qb,
                                                   const float* __restrict__ kvb,
                                                   bf16* __restrict__ qo,
                                                   bf16* __restrict__ kvo)
{
    extern __shared__ char smraw[];
    int y = blockIdx.y;
    if (y < 4)
        gemm_body<true>(xn, wq, qb, nullptr, qo, CCH,
                        blockIdx.z, y * 128, blockIdx.x * 128, smraw);
    else
        gemm_body<true>(cn, wkv, kvb, nullptr, kvo, 2 * CCH,
                        blockIdx.z, (y - 4) * 128, blockIdx.x * 128, smraw);
}

// proj GEMM (fp32 out + residual)
__global__ __launch_bounds__(256, 2) void gemm_proj(const bf16* __restrict__ in,
                                                    const bf16* __restrict__ W,
                                                    const float* __restrict__ bias,
                                                    const float* __restrict__ resid,
                                                    float* __restrict__ outp)
{
    extern __shared__ char smraw[];
    gemm_body<false>(in, W, bias, resid, outp, CCH,
                     blockIdx.z, blockIdx.y * 128, blockIdx.x * 128, smraw);
}

// ---------------- attention (R10 winner, unchanged) ----------------
#define QI 136
#define KJ 72
#define Q_BYTES (64 * QI * 2)
#define KV_BYTES (64 * KJ * 2)
#define ATTN_SMEM (Q_BYTES + 4 * KV_BYTES)

__global__ __launch_bounds__(256, 2) void attn_mma(const bf16* __restrict__ qb,
                                                   const bf16* __restrict__ kvb,
                                                   bf16* __restrict__ ob)
{
    extern __shared__ char asmraw[];
    bf16* Qs = (bf16*)asmraw;
    const unsigned int sb = smem_u32(asmraw);
    const unsigned int kbuf0 = sb + Q_BYTES;
    const unsigned int vbuf0 = sb + Q_BYTES + 2 * KV_BYTES;

    int i0 = blockIdx.x * 128;
    int h  = blockIdx.y;
    int b  = blockIdx.z;
    int tid = threadIdx.x, wid = tid >> 5, lane = tid & 31;
    int gid = lane >> 2, qtid = lane & 3;
    int ibase = wid * 16;
    int lg = lane >> 3, lr = lane & 7;

    const bf16* qp = qb  + ((size_t)b * CCH     + h * 64) * LSP;
    const bf16* kp = kvb + ((size_t)b * 2 * CCH + h * 64) * LSP;
    const bf16* vp = kvb + ((size_t)b * 2 * CCH + CCH + h * 64) * LSP;
    bf16*       op = ob  + ((size_t)b * CCH     + h * 64) * LSP;

    int dk = tid >> 2, ck4 = (tid & 3);

    auto stageKV = [&](int s, int kt) {
        const bf16* ks_ = kp + (size_t)dk * LSP + kt * 64 + ck4 * 16;
        const bf16* vs_ = vp + (size_t)dk * LSP + kt * 64 + ck4 * 16;
        unsigned int ko = kbuf0 + s * KV_BYTES + dk * (KJ * 2) + ck4 * 32;
        unsigned int vo = vbuf0 + s * KV_BYTES + dk * (KJ * 2) + ck4 * 32;
        CP_ASYNC16(ko,      ks_);
        CP_ASYNC16(ko + 16, ks_ + 8);
        CP_ASYNC16(vo,      vs_);
        CP_ASYNC16(vo + 16, vs_ + 8);
        CP_COMMIT();
    };

    stageKV(0, 0);

    {
        int d = tid >> 2, c = (tid & 3) * 32;
        const uint4* s = (const uint4*)&qp[(size_t)d * LSP + i0 + c];
        uint4* t = (uint4*)&Qs[d * QI + c];
        t[0] = s[0]; t[1] = s[1]; t[2] = s[2]; t[3] = s[3];
    }
    __syncthreads();

    unsigned int qa[4][4];
    #pragma unroll
    for (int ks = 0; ks < 4; ks++) {
        int drow = ks * 16 + (lg >> 1) * 8 + lr;
        int icol = ibase + (lg & 1) * 8;
        unsigned int a = smem_u32(&Qs[drow * QI + icol]);
        LDSM4T(qa[ks][0], qa[ks][1], qa[ks][2], qa[ks][3], a);
    }

    float oacc[8][4] = {};
    float rl = 0.f, rh = 0.f;

    for (int kt = 0; kt < 16; kt++) {
        int s = kt & 1;
        CP_WAIT0();
        __syncthreads();
        if (kt < 15) stageKV(s ^ 1, kt + 1);

        unsigned int kb = kbuf0 + s * KV_BYTES;
        unsigned int vb = vbuf0 + s * KV_BYTES;

        float sacc[8][4] = {};
        #pragma unroll
        for (int ks = 0; ks < 4; ks++) {
            #pragma unroll
            for (int jp = 0; jp < 4; jp++) {
                int drow = ks * 16 + (lg & 1) * 8 + lr;
                int jcol = jp * 16 + (lg >> 1) * 8;
                unsigned int a = kb + drow * (KJ * 2) + jcol * 2;
                unsigned int b0, b1, b2, b3;
                LDSM4T(b0, b1, b2, b3, a);
                MMA16816(sacc[jp * 2],     qa[ks], b0, b1);
                MMA16816(sacc[jp * 2 + 1], qa[ks], b2, b3);
            }
        }

        unsigned int pa[4][4];
        #pragma unroll
        for (int t = 0; t < 8; t++) {
            float e0 = __expf(sacc[t][0] * 0.125f);
            float e1 = __expf(sacc[t][1] * 0.125f);
            float e2 = __expf(sacc[t][2] * 0.125f);
            float e3 = __expf(sacc[t][3] * 0.125f);
            rl += e0 + e1;
            rh += e2 + e3;
            pa[t >> 1][(t & 1) * 2]     = packbf2(e0, e1);
            pa[t >> 1][(t & 1) * 2 + 1] = packbf2(e2, e3);
        }

        #pragma unroll
        for (int ks = 0; ks < 4; ks++) {
            #pragma unroll
            for (int dp = 0; dp < 4; dp++) {
                int drow = dp * 16 + (lg >> 1) * 8 + lr;
                int jcol = ks * 16 + (lg & 1) * 8;
                unsigned int a = vb + drow * (KJ * 2) + jcol * 2;
                unsigned int b0, b1, b2, b3;
                LDSM4(b0, b1, b2, b3, a);
                MMA16816(oacc[dp * 2],     pa[ks], b0, b1);
                MMA16816(oacc[dp * 2 + 1], pa[ks], b2, b3);
            }
        }
    }

    rl += __shfl_xor_sync(~0u, rl, 1); rl += __shfl_xor_sync(~0u, rl, 2);
    rh += __shfl_xor_sync(~0u, rh, 1); rh += __shfl_xor_sync(~0u, rh, 2);
    float il = 1.f / rl, ih = 1.f / rh;

    __syncthreads();
    #pragma unroll
    for (int t = 0; t < 8; t++) {
        int dcol = t * 8 + qtid * 2;
        Qs[dcol * QI + ibase + gid]           = __float2bfloat16(oacc[t][0] * il);
        Qs[(dcol + 1) * QI + ibase + gid]     = __float2bfloat16(oacc[t][1] * il);
        Qs[dcol * QI + ibase + gid + 8]       = __float2bfloat16(oacc[t][2] * ih);
        Qs[(dcol + 1) * QI + ibase + gid + 8] = __float2bfloat16(oacc[t][3] * ih);
    }
    __syncthreads();

    {
        int d = tid >> 2, c = (tid & 3) * 32;
        const uint4* s = (const uint4*)&Qs[d * QI + c];
        uint4* t = (uint4*)&op[(size_t)d * LSP + i0 + c];
        t[0] = s[0]; t[1] = s[1]; t[2] = s[2]; t[3] = s[3];
    }
}

// ---------------- launch ----------------
extern "C" void kernel_launch(void* const* d_in, const int* in_sizes, int n_in,
                              void* d_out, int out_size)
{
    const float* x   = (const float*)d_in[0];
    const float* ctx = (const float*)d_in[1];
    const float* nqw = (const float*)d_in[2];
    const float* nqb = (const float*)d_in[3];
    const float* nkw = (const float*)d_in[4];
    const float* nkb = (const float*)d_in[5];
    const float* cqw = (const float*)d_in[6];
    const float* cqb = (const float*)d_in[7];
    const float* ckw = (const float*)d_in[8];
    const float* ckb = (const float*)d_in[9];
    const float* pw  = (const float*)d_in[10];
    const float* pb  = (const float*)d_in[11];
    float* out = (float*)d_out;

    bf16 *xn, *cn, *q, *kv, *o, *wq, *wkv, *wp;
    cudaGetSymbolAddress((void**)&xn,  g_xn);
    cudaGetSymbolAddress((void**)&cn,  g_cn);
    cudaGetSymbolAddress((void**)&q,   g_q);
    cudaGetSymbolAddress((void**)&kv,  g_kv);
    cudaGetSymbolAddress((void**)&o,   g_o);
    cudaGetSymbolAddress((void**)&wq,  g_wq);
    cudaGetSymbolAddress((void**)&wkv, g_wkv);
    cudaGetSymbolAddress((void**)&wp,  g_wp);

    const int gsmem = 6 * A_ST;   // 98304 B
    cudaFuncSetAttribute(gemm_qkv,  cudaFuncAttributeMaxDynamicSharedMemorySize, gsmem);
    cudaFuncSetAttribute(gemm_proj, cudaFuncAttributeMaxDynamicSharedMemorySize, gsmem);
    cudaFuncSetAttribute(attn_mma,  cudaFuncAttributeMaxDynamicSharedMemorySize, ATTN_SMEM);

    const int nq = CCH * CCH / 4, nkv = 2 * CCH * CCH / 4;
    const int cvt_blocks = (nq + nkv + nq + 255) / 256;   // 1024

    head_kernel<<<2 * BATCH * 32 + cvt_blocks, 256>>>(
        x, nqw, nqb, xn, ctx, nkw, nkb, cn,
        cqw, wq, nq, ckw, wkv, nkv, pw, wp, nq);

    gemm_qkv<<<dim3(8, 12, BATCH), 256, gsmem>>>(xn, cn, wq, wkv, cqb, ckb, q, kv);

    attn_mma<<<dim3(8, NHEADS, BATCH), 256, ATTN_SMEM>>>(q, kv, o);

    gemm_proj<<<dim3(8, 4, BATCH), 256, gsmem>>>(o, wp, pb, x, out);
}